// round 12
// baseline (speedup 1.0000x reference)
#include <cuda_runtime.h>
#include <math.h>
#include <stdint.h>

// Problem constants
#define NT   1024          // tokens
#define ND   2048          // hidden dim
#define NE   32            // experts
#define NI   1408          // routed intermediate
#define NSI  2816          // shared intermediate
#define NG   8             // groups
#define EPG  4             // experts per group
#define NA   (NT * 4)      // total assignments (top_k = 4)

// ---------------- device scratch ----------------
__device__ float g_h [NA * NI];    // routed  silu(x@Wg)*(x@Wu)  (fp32)
__device__ float g_hs[NT * NSI];   // shared  silu(x@Sg)*(x@Su)
__device__ int   g_rowlist[NA];
__device__ float g_roww  [NA];
__device__ int   g_counts [NE];
__device__ int   g_offsets[NE];
__device__ int   g_cursor [NE];
__device__ int   g_tid4[NA];
__device__ float g_tw4 [NA];

// ---------------- bf16 split + mma helpers ----------------
__device__ __forceinline__ void split2(float v0, float v1, unsigned& h, unsigned& l) {
    unsigned hh;
    asm("cvt.rn.bf16x2.f32 %0, %1, %2;" : "=r"(hh) : "f"(v1), "f"(v0));
    float h0 = __uint_as_float(hh << 16);
    float h1 = __uint_as_float(hh & 0xffff0000u);
    asm("cvt.rn.bf16x2.f32 %0, %1, %2;" : "=r"(l) : "f"(v1 - h1), "f"(v0 - h0));
    h = hh;
}

__device__ __forceinline__ void mma_bf16(float* d, const unsigned* a, const unsigned* b) {
    asm volatile(
        "mma.sync.aligned.m16n8k16.row.col.f32.bf16.bf16.f32 "
        "{%0,%1,%2,%3}, {%4,%5,%6,%7}, {%8,%9}, {%0,%1,%2,%3};"
        : "+f"(d[0]), "+f"(d[1]), "+f"(d[2]), "+f"(d[3])
        : "r"(a[0]), "r"(a[1]), "r"(a[2]), "r"(a[3]), "r"(b[0]), "r"(b[1]));
}

__device__ __forceinline__ void ldsm4(unsigned* r, uint32_t a) {
    asm volatile("ldmatrix.sync.aligned.m8n8.x4.shared.b16 {%0,%1,%2,%3}, [%4];"
        : "=r"(r[0]), "=r"(r[1]), "=r"(r[2]), "=r"(r[3]) : "r"(a));
}
__device__ __forceinline__ void ldsm4t(unsigned* r, uint32_t a) {
    asm volatile("ldmatrix.sync.aligned.m8n8.x4.trans.shared.b16 {%0,%1,%2,%3}, [%4];"
        : "=r"(r[0]), "=r"(r[1]), "=r"(r[2]), "=r"(r[3]) : "r"(a));
}
__device__ __forceinline__ uint32_t sptr(const void* p) {
    return (uint32_t)__cvta_generic_to_shared(p);
}

// ---------------- routing kernels ----------------
__global__ void zero_kernel() {
    int i = threadIdx.x;
    if (i < NE) { g_counts[i] = 0; g_cursor[i] = 0; }
}

__global__ void gate_kernel(const float* __restrict__ x,
                            const float* __restrict__ gw,
                            const float* __restrict__ gb) {
    __shared__ float xs[ND];
    __shared__ float logit[NE];
    int t = blockIdx.x;
    for (int k = threadIdx.x; k < ND; k += 256) xs[k] = x[(size_t)t * ND + k];
    __syncthreads();
    int e = threadIdx.x >> 3;
    int j = threadIdx.x & 7;
    const float* w = gw + (size_t)e * ND;
    float s = 0.f;
    for (int k = j; k < ND; k += 8) s += xs[k] * w[k];
    s += __shfl_xor_sync(0xffffffffu, s, 1);
    s += __shfl_xor_sync(0xffffffffu, s, 2);
    s += __shfl_xor_sync(0xffffffffu, s, 4);
    if (j == 0) logit[e] = s + gb[e];
    __syncthreads();
    if (threadIdx.x == 0) {
        float sc[NE], scb[NE];
        #pragma unroll
        for (int i = 0; i < NE; i++) {
            float v = 1.f / (1.f + expf(-logit[i]));
            sc[i]  = v;
            scb[i] = v + gb[i];
        }
        float gs[NG];
        #pragma unroll
        for (int g = 0; g < NG; g++) {
            float m1 = -1e30f, m2 = -1e30f;
            #pragma unroll
            for (int q = 0; q < EPG; q++) {
                float v = scb[g * EPG + q];
                if (v > m1) { m2 = m1; m1 = v; } else if (v > m2) { m2 = v; }
            }
            gs[g] = m1 + m2;
        }
        bool gsel[NG];
        #pragma unroll
        for (int g = 0; g < NG; g++) gsel[g] = false;
        for (int r = 0; r < 4; r++) {
            float best = -1e30f; int bi = 0;
            for (int g = 0; g < NG; g++)
                if (!gsel[g] && gs[g] > best) { best = gs[g]; bi = g; }
            gsel[bi] = true;
        }
        float tmp[NE];
        #pragma unroll
        for (int i = 0; i < NE; i++) tmp[i] = gsel[i / EPG] ? scb[i] : 0.0f;
        int ids[4]; float tw[4]; float wsum = 0.f;
        for (int r = 0; r < 4; r++) {
            float best = -1e30f; int bi = 0;
            for (int i = 0; i < NE; i++)
                if (tmp[i] > best) { best = tmp[i]; bi = i; }
            tmp[bi] = -1e30f;
            ids[r] = bi;
            tw[r] = sc[bi];
            wsum += tw[r];
        }
        float inv = 1.f / wsum;
        for (int r = 0; r < 4; r++) {
            g_tid4[t * 4 + r] = ids[r];
            g_tw4 [t * 4 + r] = tw[r] * inv;
            atomicAdd(&g_counts[ids[r]], 1);
        }
    }
}

__global__ void scan_kernel() {
    int tid = threadIdx.x;
    int c = g_counts[tid];
    int v = c;
    #pragma unroll
    for (int o = 1; o < 32; o <<= 1) {
        int u = __shfl_up_sync(0xffffffffu, v, o);
        if (tid >= o) v += u;
    }
    g_offsets[tid] = v - c;
}

__global__ void scatter_kernel() {
    int i = blockIdx.x * blockDim.x + threadIdx.x;
    if (i >= NA) return;
    int t = i >> 2;
    int e = g_tid4[i];
    int pos = atomicAdd(&g_cursor[e], 1);
    int row = g_offsets[e] + pos;
    g_rowlist[row] = t;
    g_roww[row]   = g_tw4[i];
}

// ============================================================================
// bf16x3 mma.sync GEMMs, LDSM fragments, 4-stage SMEM ring, 1 sync / 2 chunks.
// Block BM=128, BN=64, BK=16; 256 thr = 8 warps (4M x 2N); warp tile 32x32.
// A SMEM stage: [128][24 bf16] (stride 48B, LDSM conflict-free; cols 0..15)
// B SMEM stage: [16][72 bf16]  (stride 144B, conflict-free; cols 0..63)
// Dynamic SMEM: gated 84KB, down 66KB; 2 CTAs/SM.
// ============================================================================

#define A_STR 24
#define B_STR 72
#define A_SZ  (128 * A_STR)
#define B_SZ  (16 * B_STR)
#define A_SZB (A_SZ * 2)
#define B_SZB (B_SZ * 2)

// gated smem offsets
#define GOF_AH  0
#define GOF_AL  (4 * A_SZB)
#define GOF_BGH (8 * A_SZB)
#define GOF_BGL (GOF_BGH + 4 * B_SZB)
#define GOF_BUH (GOF_BGL + 4 * B_SZB)
#define GOF_BUL (GOF_BUH + 4 * B_SZB)
#define SM_GATED (GOF_BUL + 4 * B_SZB)   // 86016
// down smem offsets
#define DOF_AH  0
#define DOF_AL  (4 * A_SZB)
#define DOF_BH  (8 * A_SZB)
#define DOF_BL  (DOF_BH + 4 * B_SZB)
#define SM_DOWN (DOF_BL + 4 * B_SZB)     // 67584

// ---------------- GEMM 1: H = silu(A@Wg) * (A@Wu) ----------------
template<int IDIM, bool GATHER>
__global__ void __launch_bounds__(256, 2)
gemm_gated(const float* __restrict__ x,
           const float* __restrict__ Wg,
           const float* __restrict__ Wu) {
    extern __shared__ char dsm[];
    int e   = GATHER ? blockIdx.z : 0;
    int cnt = GATHER ? g_counts[e]  : NT;
    int off = GATHER ? g_offsets[e] : 0;
    int m0  = blockIdx.x * 128;
    if (m0 >= cnt) return;
    int n0  = blockIdx.y * 64;
    float* H = GATHER ? g_h : g_hs;

    int tid  = threadIdx.x;
    int lane = tid & 31, wid = tid >> 5;
    int warpM = wid >> 1, warpN = wid & 1;
    int gq = lane >> 2, tq = lane & 3;

    // ---- A staging: 2 float4 per thread over 128x16 fp32 ----
    const float* aptr[2]; int mA[2], kA[2];
    #pragma unroll
    for (int l = 0; l < 2; l++) {
        int idx = tid + l * 256;
        mA[l] = idx >> 2; kA[l] = (idx & 3) << 2;
        int m = m0 + mA[l];
        int tok;
        if (GATHER) tok = (m < cnt) ? g_rowlist[off + m] : 0;
        else        tok = (m < cnt) ? m : 0;
        aptr[l] = x + (size_t)tok * ND + kA[l];
    }
    // ---- B staging: 2 matrices x 128 threads; rows kr, kr+8; 4 n-vals ----
    int mat = tid >> 7, rr = tid & 127;
    int kr  = rr >> 4, nq = (rr & 15) << 2;
    const float* bp = (mat ? Wu : Wg) + (size_t)e * ND * IDIM
                      + (size_t)kr * IDIM + n0 + nq;
    const int bofH = mat ? GOF_BUH : GOF_BGH;
    const int bofL = mat ? GOF_BUL : GOF_BGL;

    // ---- LDSM base addresses (stage 0) ----
    uint32_t sbase = sptr(dsm);
    int arow = lane & 15, acolb = (lane >> 4) << 4;
    uint32_t a_ld_h[2], a_ld_l[2];
    #pragma unroll
    for (int mt = 0; mt < 2; mt++) {
        int r = warpM * 32 + mt * 16 + arow;
        a_ld_h[mt] = sbase + GOF_AH + r * (A_STR * 2) + acolb;
        a_ld_l[mt] = sbase + GOF_AL + r * (A_STR * 2) + acolb;
    }
    int bkr = lane & 15;
    int bcolb = (warpN * 32) * 2 + ((lane >> 4) << 4);
    uint32_t b_ld[4][2];
    const int bofs[4] = {GOF_BGH, GOF_BGL, GOF_BUH, GOF_BUL};
    #pragma unroll
    for (int a = 0; a < 4; a++)
        #pragma unroll
        for (int np = 0; np < 2; np++)
            b_ld[a][np] = sbase + bofs[a] + bkr * (B_STR * 2) + bcolb + np * 32;

    float accg[2][4][4], accu[2][4][4];
    #pragma unroll
    for (int mt = 0; mt < 2; mt++)
        #pragma unroll
        for (int nt = 0; nt < 4; nt++)
            #pragma unroll
            for (int r = 0; r < 4; r++) { accg[mt][nt][r] = 0.f; accu[mt][nt][r] = 0.f; }

    float4 ra0, ra1, rb0, rb1;

    auto load_chunk = [&](int c) {
        int kt = c * 16;
        ra0 = *(const float4*)(aptr[0] + kt);
        ra1 = *(const float4*)(aptr[1] + kt);
        rb0 = *(const float4*)(bp + (size_t)kt * IDIM);
        rb1 = *(const float4*)(bp + (size_t)(kt + 8) * IDIM);
    };
    auto store_stage = [&](int s) {
        unsigned short* AhS = (unsigned short*)(dsm + GOF_AH + s * A_SZB);
        unsigned short* AlS = (unsigned short*)(dsm + GOF_AL + s * A_SZB);
        unsigned short* BHS = (unsigned short*)(dsm + bofH + s * B_SZB);
        unsigned short* BLS = (unsigned short*)(dsm + bofL + s * B_SZB);
        unsigned h0, l0, h1, l1;
        split2(ra0.x, ra0.y, h0, l0); split2(ra0.z, ra0.w, h1, l1);
        *(uint2*)&AhS[mA[0] * A_STR + kA[0]] = make_uint2(h0, h1);
        *(uint2*)&AlS[mA[0] * A_STR + kA[0]] = make_uint2(l0, l1);
        split2(ra1.x, ra1.y, h0, l0); split2(ra1.z, ra1.w, h1, l1);
        *(uint2*)&AhS[mA[1] * A_STR + kA[1]] = make_uint2(h0, h1);
        *(uint2*)&AlS[mA[1] * A_STR + kA[1]] = make_uint2(l0, l1);
        split2(rb0.x, rb0.y, h0, l0); split2(rb0.z, rb0.w, h1, l1);
        *(uint2*)&BHS[kr * B_STR + nq] = make_uint2(h0, h1);
        *(uint2*)&BLS[kr * B_STR + nq] = make_uint2(l0, l1);
        split2(rb1.x, rb1.y, h0, l0); split2(rb1.z, rb1.w, h1, l1);
        *(uint2*)&BHS[(kr + 8) * B_STR + nq] = make_uint2(h0, h1);
        *(uint2*)&BLS[(kr + 8) * B_STR + nq] = make_uint2(l0, l1);
    };
    auto do_mma = [&](int s) {
        uint32_t ao = s * A_SZB, bo = s * B_SZB;
        unsigned ah[2][4], al[2][4];
        ldsm4(ah[0], a_ld_h[0] + ao); ldsm4(ah[1], a_ld_h[1] + ao);
        ldsm4(al[0], a_ld_l[0] + ao); ldsm4(al[1], a_ld_l[1] + ao);
        #pragma unroll
        for (int np = 0; np < 2; np++) {
            unsigned bgh[4], bgl[4], buh[4], bul[4];
            ldsm4t(bgh, b_ld[0][np] + bo); ldsm4t(bgl, b_ld[1][np] + bo);
            ldsm4t(buh, b_ld[2][np] + bo); ldsm4t(bul, b_ld[3][np] + bo);
            #pragma unroll
            for (int j = 0; j < 2; j++) {
                int nt = np * 2 + j;
                #pragma unroll
                for (int mt = 0; mt < 2; mt++) {
                    mma_bf16(accg[mt][nt], ah[mt], &bgh[2 * j]);
                    mma_bf16(accg[mt][nt], al[mt], &bgh[2 * j]);
                    mma_bf16(accg[mt][nt], ah[mt], &bgl[2 * j]);
                    mma_bf16(accu[mt][nt], ah[mt], &buh[2 * j]);
                    mma_bf16(accu[mt][nt], al[mt], &buh[2 * j]);
                    mma_bf16(accu[mt][nt], ah[mt], &bul[2 * j]);
                }
            }
        }
    };

    // prologue: chunks 0,1 -> stages 0,1
    load_chunk(0); store_stage(0);
    load_chunk(1); store_stage(1);
    __syncthreads();

    const int NCH = ND / 16;   // even
    for (int c = 0; c < NCH; c += 2) {
        bool more = (c + 2 < NCH);
        if (more) load_chunk(c + 2);
        do_mma(c & 3);
        if (more) store_stage((c + 2) & 3);
        if (more) load_chunk(c + 3);
        do_mma((c + 1) & 3);
        if (more) store_stage((c + 3) & 3);
        __syncthreads();
    }

    // epilogue: silu(gate) * up -> fp32 H
    #pragma unroll
    for (int mt = 0; mt < 2; mt++) {
        #pragma unroll
        for (int half = 0; half < 2; half++) {
            int r = m0 + warpM * 32 + mt * 16 + half * 8 + gq;
            if (r >= cnt) continue;
            float* hrow = H + (size_t)(off + r) * IDIM + n0 + warpN * 32;
            #pragma unroll
            for (int nt = 0; nt < 4; nt++) {
                float gv0 = accg[mt][nt][half * 2 + 0];
                float gv1 = accg[mt][nt][half * 2 + 1];
                float uv0 = accu[mt][nt][half * 2 + 0];
                float uv1 = accu[mt][nt][half * 2 + 1];
                float2 hv;
                hv.x = gv0 / (1.f + expf(-gv0)) * uv0;
                hv.y = gv1 / (1.f + expf(-gv1)) * uv1;
                *(float2*)&hrow[nt * 8 + 2 * tq] = hv;
            }
        }
    }
}

// ---------------- GEMM 2: out (+)= H @ Wd ----------------
template<int IDIM, bool ROUTED>
__global__ void __launch_bounds__(256, 2)
gemm_down(const float* __restrict__ Wd,
          float* __restrict__ out) {
    extern __shared__ char dsm[];
    int e   = ROUTED ? blockIdx.z : 0;
    int cnt = ROUTED ? g_counts[e]  : NT;
    int off = ROUTED ? g_offsets[e] : 0;
    int m0  = blockIdx.x * 128;
    if (m0 >= cnt) return;
    int n0  = blockIdx.y * 64;
    const float* wd = Wd + (size_t)e * IDIM * ND;
    const float* Hsrc = ROUTED ? g_h : g_hs;

    int tid  = threadIdx.x;
    int lane = tid & 31, wid = tid >> 5;
    int warpM = wid >> 1, warpN = wid & 1;
    int gq = lane >> 2, tq = lane & 3;

    const float* aptr[2]; int mA[2], kA[2];
    #pragma unroll
    for (int l = 0; l < 2; l++) {
        int idx = tid + l * 256;
        mA[l] = idx >> 2; kA[l] = (idx & 3) << 2;
        int m = m0 + mA[l];
        int hr = (m < cnt) ? (off + m) : off;
        aptr[l] = Hsrc + (size_t)hr * IDIM + kA[l];
    }
    int kr = tid >> 4, nq = (tid & 15) << 2;
    const float* bp = wd + (size_t)kr * ND + n0 + nq;

    uint32_t sbase = sptr(dsm);
    int arow = lane & 15, acolb = (lane >> 4) << 4;
    uint32_t a_ld_h[2], a_ld_l[2];
    #pragma unroll
    for (int mt = 0; mt < 2; mt++) {
        int r = warpM * 32 + mt * 16 + arow;
        a_ld_h[mt] = sbase + DOF_AH + r * (A_STR * 2) + acolb;
        a_ld_l[mt] = sbase + DOF_AL + r * (A_STR * 2) + acolb;
    }
    int bkr = lane & 15;
    int bcolb = (warpN * 32) * 2 + ((lane >> 4) << 4);
    uint32_t b_ld_h[2], b_ld_l[2];
    #pragma unroll
    for (int np = 0; np < 2; np++) {
        b_ld_h[np] = sbase + DOF_BH + bkr * (B_STR * 2) + bcolb + np * 32;
        b_ld_l[np] = sbase + DOF_BL + bkr * (B_STR * 2) + bcolb + np * 32;
    }

    float acc[2][4][4];
    #pragma unroll
    for (int mt = 0; mt < 2; mt++)
        #pragma unroll
        for (int nt = 0; nt < 4; nt++)
            #pragma unroll
            for (int r = 0; r < 4; r++) acc[mt][nt][r] = 0.f;

    float4 ra0, ra1, rb;

    auto load_chunk = [&](int c) {
        int kt = c * 16;
        ra0 = *(const float4*)(aptr[0] + kt);
        ra1 = *(const float4*)(aptr[1] + kt);
        rb  = *(const float4*)(bp + (size_t)kt * ND);
    };
    auto store_stage = [&](int s) {
        unsigned short* AhS = (unsigned short*)(dsm + DOF_AH + s * A_SZB);
        unsigned short* AlS = (unsigned short*)(dsm + DOF_AL + s * A_SZB);
        unsigned short* BHS = (unsigned short*)(dsm + DOF_BH + s * B_SZB);
        unsigned short* BLS = (unsigned short*)(dsm + DOF_BL + s * B_SZB);
        unsigned h0, l0, h1, l1;
        split2(ra0.x, ra0.y, h0, l0); split2(ra0.z, ra0.w, h1, l1);
        *(uint2*)&AhS[mA[0] * A_STR + kA[0]] = make_uint2(h0, h1);
        *(uint2*)&AlS[mA[0] * A_STR + kA[0]] = make_uint2(l0, l1);
        split2(ra1.x, ra1.y, h0, l0); split2(ra1.z, ra1.w, h1, l1);
        *(uint2*)&AhS[mA[1] * A_STR + kA[1]] = make_uint2(h0, h1);
        *(uint2*)&AlS[mA[1] * A_STR + kA[1]] = make_uint2(l0, l1);
        split2(rb.x, rb.y, h0, l0); split2(rb.z, rb.w, h1, l1);
        *(uint2*)&BHS[kr * B_STR + nq] = make_uint2(h0, h1);
        *(uint2*)&BLS[kr * B_STR + nq] = make_uint2(l0, l1);
    };
    auto do_mma = [&](int s) {
        uint32_t ao = s * A_SZB, bo = s * B_SZB;
        unsigned ah[2][4], al[2][4];
        ldsm4(ah[0], a_ld_h[0] + ao); ldsm4(ah[1], a_ld_h[1] + ao);
        ldsm4(al[0], a_ld_l[0] + ao); ldsm4(al[1], a_ld_l[1] + ao);
        #pragma unroll
        for (int np = 0; np < 2; np++) {
            unsigned bh[4], bl[4];
            ldsm4t(bh, b_ld_h[np] + bo); ldsm4t(bl, b_ld_l[np] + bo);
            #pragma unroll
            for (int j = 0; j < 2; j++) {
                int nt = np * 2 + j;
                #pragma unroll
                for (int mt = 0; mt < 2; mt++) {
                    mma_bf16(acc[mt][nt], ah[mt], &bh[2 * j]);
                    mma_bf16(acc[mt][nt], al[mt], &bh[2 * j]);
                    mma_bf16(acc[mt][nt], ah[mt], &bl[2 * j]);
                }
            }
        }
    };

    load_chunk(0); store_stage(0);
    load_chunk(1); store_stage(1);
    __syncthreads();

    const int NCH = IDIM / 16;  // 88 or 176, even
    for (int c = 0; c < NCH; c += 2) {
        bool more = (c + 2 < NCH);
        if (more) load_chunk(c + 2);
        do_mma(c & 3);
        if (more) store_stage((c + 2) & 3);
        if (more) load_chunk(c + 3);
        do_mma((c + 1) & 3);
        if (more) store_stage((c + 3) & 3);
        __syncthreads();
    }

    // epilogue
    #pragma unroll
    for (int mt = 0; mt < 2; mt++) {
        #pragma unroll
        for (int half = 0; half < 2; half++) {
            int r = m0 + warpM * 32 + mt * 16 + half * 8 + gq;
            if (r >= cnt) continue;
            if (ROUTED) {
                int grow = off + r;
                int tok  = g_rowlist[grow];
                float w  = g_roww[grow] * 2.5f;
                float* op = out + (size_t)tok * ND + n0 + warpN * 32;
                #pragma unroll
                for (int nt = 0; nt < 4; nt++) {
                    atomicAdd(&op[nt * 8 + 2 * tq],     w * acc[mt][nt][half * 2 + 0]);
                    atomicAdd(&op[nt * 8 + 2 * tq + 1], w * acc[mt][nt][half * 2 + 1]);
                }
            } else {
                float* op = out + (size_t)r * ND + n0 + warpN * 32;
                #pragma unroll
                for (int nt = 0; nt < 4; nt++) {
                    float2 v;
                    v.x = acc[mt][nt][half * 2 + 0];
                    v.y = acc[mt][nt][half * 2 + 1];
                    *(float2*)&op[nt * 8 + 2 * tq] = v;
                }
            }
        }
    }
}

// ---------------- launch ----------------
extern "C" void kernel_launch(void* const* d_in, const int* in_sizes, int n_in,
                              void* d_out, int out_size) {
    const float* x       = (const float*)d_in[0];
    const float* gate_w  = (const float*)d_in[1];
    const float* gate_b  = (const float*)d_in[2];
    const float* w_gate  = (const float*)d_in[3];
    const float* w_up    = (const float*)d_in[4];
    const float* w_down  = (const float*)d_in[5];
    const float* sw_gate = (const float*)d_in[6];
    const float* sw_up   = (const float*)d_in[7];
    const float* sw_down = (const float*)d_in[8];
    float* out = (float*)d_out;

    cudaFuncSetAttribute(gemm_gated<NSI, false>, cudaFuncAttributeMaxDynamicSharedMemorySize, SM_GATED);
    cudaFuncSetAttribute(gemm_gated<NI,  true >, cudaFuncAttributeMaxDynamicSharedMemorySize, SM_GATED);
    cudaFuncSetAttribute(gemm_down<NSI, false>, cudaFuncAttributeMaxDynamicSharedMemorySize, SM_DOWN);
    cudaFuncSetAttribute(gemm_down<NI,  true >, cudaFuncAttributeMaxDynamicSharedMemorySize, SM_DOWN);

    zero_kernel   <<<1, 32>>>();
    gate_kernel   <<<NT, 256>>>(x, gate_w, gate_b);
    scan_kernel   <<<1, 32>>>();
    scatter_kernel<<<NA / 256, 256>>>();

    // shared expert gate/up
    gemm_gated<NSI, false><<<dim3(NT / 128, NSI / 64, 1), 256, SM_GATED>>>(x, sw_gate, sw_up);
    // routed experts gate/up
    gemm_gated<NI,  true ><<<dim3(NT / 128, NI  / 64, NE), 256, SM_GATED>>>(x, w_gate, w_up);
    // shared down-proj: plain stores initialize out
    gemm_down<NSI, false><<<dim3(NT / 128, ND / 64, 1), 256, SM_DOWN>>>(sw_down, out);
    // routed down-proj: weighted atomic accumulation
    gemm_down<NI,  true ><<<dim3(NT / 128, ND / 64, NE), 256, SM_DOWN>>>(w_down, out);
}

// round 13
// speedup vs baseline: 1.0561x; 1.0561x over previous
#include <cuda_runtime.h>
#include <math.h>
#include <stdint.h>

// Problem constants
#define NT   1024          // tokens
#define ND   2048          // hidden dim
#define NE   32            // experts
#define NI   1408          // routed intermediate
#define NSI  2816          // shared intermediate
#define NG   8             // groups
#define EPG  4             // experts per group
#define NA   (NT * 4)      // total assignments (top_k = 4)

// ---------------- device scratch ----------------
__device__ float g_h [NA * NI];    // routed  silu(x@Wg)*(x@Wu)  (fp32)
__device__ float g_hs[NT * NSI];   // shared  silu(x@Sg)*(x@Su)
__device__ int   g_rowlist[NA];
__device__ float g_roww  [NA];
__device__ int   g_counts [NE];
__device__ int   g_offsets[NE];
__device__ int   g_cursor [NE];
__device__ int   g_tid4[NA];
__device__ float g_tw4 [NA];

// ---------------- bf16 split + mma helpers ----------------
__device__ __forceinline__ void split2(float v0, float v1, unsigned& h, unsigned& l) {
    unsigned hh;
    asm("cvt.rn.bf16x2.f32 %0, %1, %2;" : "=r"(hh) : "f"(v1), "f"(v0));
    float h0 = __uint_as_float(hh << 16);
    float h1 = __uint_as_float(hh & 0xffff0000u);
    asm("cvt.rn.bf16x2.f32 %0, %1, %2;" : "=r"(l) : "f"(v1 - h1), "f"(v0 - h0));
    h = hh;
}

__device__ __forceinline__ void mma_bf16(float* d, const unsigned* a, const unsigned* b) {
    asm volatile(
        "mma.sync.aligned.m16n8k16.row.col.f32.bf16.bf16.f32 "
        "{%0,%1,%2,%3}, {%4,%5,%6,%7}, {%8,%9}, {%0,%1,%2,%3};"
        : "+f"(d[0]), "+f"(d[1]), "+f"(d[2]), "+f"(d[3])
        : "r"(a[0]), "r"(a[1]), "r"(a[2]), "r"(a[3]), "r"(b[0]), "r"(b[1]));
}

__device__ __forceinline__ void ldsm4(unsigned* r, uint32_t a) {
    asm volatile("ldmatrix.sync.aligned.m8n8.x4.shared.b16 {%0,%1,%2,%3}, [%4];"
        : "=r"(r[0]), "=r"(r[1]), "=r"(r[2]), "=r"(r[3]) : "r"(a));
}
__device__ __forceinline__ void ldsm4t(unsigned* r, uint32_t a) {
    asm volatile("ldmatrix.sync.aligned.m8n8.x4.trans.shared.b16 {%0,%1,%2,%3}, [%4];"
        : "=r"(r[0]), "=r"(r[1]), "=r"(r[2]), "=r"(r[3]) : "r"(a));
}
__device__ __forceinline__ uint32_t sptr(const void* p) {
    return (uint32_t)__cvta_generic_to_shared(p);
}

// ---------------- routing kernels ----------------
__global__ void zero_kernel() {
    int i = threadIdx.x;
    if (i < NE) { g_counts[i] = 0; g_cursor[i] = 0; }
}

__global__ void gate_kernel(const float* __restrict__ x,
                            const float* __restrict__ gw,
                            const float* __restrict__ gb) {
    __shared__ float xs[ND];
    __shared__ float logit[NE];
    int t = blockIdx.x;
    for (int k = threadIdx.x; k < ND; k += 256) xs[k] = x[(size_t)t * ND + k];
    __syncthreads();
    int e = threadIdx.x >> 3;
    int j = threadIdx.x & 7;
    const float* w = gw + (size_t)e * ND;
    float s = 0.f;
    for (int k = j; k < ND; k += 8) s += xs[k] * w[k];
    s += __shfl_xor_sync(0xffffffffu, s, 1);
    s += __shfl_xor_sync(0xffffffffu, s, 2);
    s += __shfl_xor_sync(0xffffffffu, s, 4);
    if (j == 0) logit[e] = s + gb[e];
    __syncthreads();
    if (threadIdx.x == 0) {
        float sc[NE], scb[NE];
        #pragma unroll
        for (int i = 0; i < NE; i++) {
            float v = 1.f / (1.f + expf(-logit[i]));
            sc[i]  = v;
            scb[i] = v + gb[i];
        }
        float gs[NG];
        #pragma unroll
        for (int g = 0; g < NG; g++) {
            float m1 = -1e30f, m2 = -1e30f;
            #pragma unroll
            for (int q = 0; q < EPG; q++) {
                float v = scb[g * EPG + q];
                if (v > m1) { m2 = m1; m1 = v; } else if (v > m2) { m2 = v; }
            }
            gs[g] = m1 + m2;
        }
        bool gsel[NG];
        #pragma unroll
        for (int g = 0; g < NG; g++) gsel[g] = false;
        for (int r = 0; r < 4; r++) {
            float best = -1e30f; int bi = 0;
            for (int g = 0; g < NG; g++)
                if (!gsel[g] && gs[g] > best) { best = gs[g]; bi = g; }
            gsel[bi] = true;
        }
        float tmp[NE];
        #pragma unroll
        for (int i = 0; i < NE; i++) tmp[i] = gsel[i / EPG] ? scb[i] : 0.0f;
        int ids[4]; float tw[4]; float wsum = 0.f;
        for (int r = 0; r < 4; r++) {
            float best = -1e30f; int bi = 0;
            for (int i = 0; i < NE; i++)
                if (tmp[i] > best) { best = tmp[i]; bi = i; }
            tmp[bi] = -1e30f;
            ids[r] = bi;
            tw[r] = sc[bi];
            wsum += tw[r];
        }
        float inv = 1.f / wsum;
        for (int r = 0; r < 4; r++) {
            g_tid4[t * 4 + r] = ids[r];
            g_tw4 [t * 4 + r] = tw[r] * inv;
            atomicAdd(&g_counts[ids[r]], 1);
        }
    }
}

__global__ void scan_kernel() {
    int tid = threadIdx.x;
    int c = g_counts[tid];
    int v = c;
    #pragma unroll
    for (int o = 1; o < 32; o <<= 1) {
        int u = __shfl_up_sync(0xffffffffu, v, o);
        if (tid >= o) v += u;
    }
    g_offsets[tid] = v - c;
}

__global__ void scatter_kernel() {
    int i = blockIdx.x * blockDim.x + threadIdx.x;
    if (i >= NA) return;
    int t = i >> 2;
    int e = g_tid4[i];
    int pos = atomicAdd(&g_cursor[e], 1);
    int row = g_offsets[e] + pos;
    g_rowlist[row] = t;
    g_roww[row]   = g_tw4[i];
}

// ============================================================================
// bf16x3 mma.sync GEMMs, LDSM fragments, 2-stage ping-pong (R11 structure).
// SINGLE launch covers routed experts (z<32) AND shared expert (z==32):
// runtime idim selects B column stride / H row stride; routed n-blocks beyond
// NI exit early. This fills the shared expert's wave-quantization gap.
// Block BM=128, BN=64, BK=16; 256 thr = 8 warps (4M x 2N); warp tile 32x32.
// ============================================================================

#define A_STR 24
#define B_STR 72
#define A_SZ  (128 * A_STR)
#define B_SZ  (16 * B_STR)
#define A_SZB (A_SZ * 2)
#define B_SZB (B_SZ * 2)

// ---------------- GEMM 1: H = silu(A@Wg) * (A@Wu) ----------------
__global__ void __launch_bounds__(256, 2)
gemm_gated_all(const float* __restrict__ x,
               const float* __restrict__ Wg,  const float* __restrict__ Wu,
               const float* __restrict__ SWg, const float* __restrict__ SWu) {
    int z = blockIdx.z;
    bool shared_e = (z == NE);
    int cnt, off, idim;
    const float* wg;
    const float* wu;
    float* H;
    if (shared_e) {
        cnt = NT; off = 0; idim = NSI;
        wg = SWg; wu = SWu; H = g_hs;
    } else {
        cnt = g_counts[z]; off = g_offsets[z]; idim = NI;
        wg = Wg + (size_t)z * ND * NI;
        wu = Wu + (size_t)z * ND * NI;
        H = g_h;
        if (blockIdx.y * 64 >= NI) return;   // routed uses only NI/64 n-blocks
    }
    int m0 = blockIdx.x * 128;
    if (m0 >= cnt) return;
    int n0 = blockIdx.y * 64;

    __shared__ __align__(16) unsigned short Ah[2][A_SZ], Al[2][A_SZ];
    __shared__ __align__(16) unsigned short Bgh[2][B_SZ], Bgl[2][B_SZ];
    __shared__ __align__(16) unsigned short Buh[2][B_SZ], Bul[2][B_SZ];

    int tid  = threadIdx.x;
    int lane = tid & 31, wid = tid >> 5;
    int warpM = wid >> 1, warpN = wid & 1;
    int gq = lane >> 2, tq = lane & 3;

    // ---- A staging: 2 float4 per thread over 128x16 fp32 ----
    const float* aptr[2]; int mA[2], kA[2];
    #pragma unroll
    for (int l = 0; l < 2; l++) {
        int idx = tid + l * 256;
        mA[l] = idx >> 2; kA[l] = (idx & 3) << 2;
        int m = m0 + mA[l];
        int tok;
        if (shared_e) tok = (m < cnt) ? m : 0;
        else          tok = (m < cnt) ? g_rowlist[off + m] : 0;
        aptr[l] = x + (size_t)tok * ND + kA[l];
    }
    // ---- B staging: 2 matrices x 128 threads; rows kr, kr+8; 4 n-vals ----
    int mat = tid >> 7, rr = tid & 127;
    int kr  = rr >> 4, nq = (rr & 15) << 2;
    const float* bp = (mat ? wu : wg) + (size_t)kr * idim + n0 + nq;
    unsigned short* BH0 = mat ? Buh[0] : Bgh[0];
    unsigned short* BL0 = mat ? Bul[0] : Bgl[0];

    // ---- LDSM base addresses ----
    int arow = lane & 15, acolb = (lane >> 4) << 4;
    uint32_t a_ld_h[2], a_ld_l[2];
    #pragma unroll
    for (int mt = 0; mt < 2; mt++) {
        int r = warpM * 32 + mt * 16 + arow;
        a_ld_h[mt] = sptr(Ah) + r * (A_STR * 2) + acolb;
        a_ld_l[mt] = sptr(Al) + r * (A_STR * 2) + acolb;
    }
    int bkr = lane & 15;
    int bcolb = (warpN * 32) * 2 + ((lane >> 4) << 4);
    uint32_t b_ld[4][2];
    const void* barr[4] = {Bgh, Bgl, Buh, Bul};
    #pragma unroll
    for (int a = 0; a < 4; a++)
        #pragma unroll
        for (int np = 0; np < 2; np++)
            b_ld[a][np] = sptr(barr[a]) + bkr * (B_STR * 2) + bcolb + np * 32;

    float accg[2][4][4], accu[2][4][4];
    #pragma unroll
    for (int mt = 0; mt < 2; mt++)
        #pragma unroll
        for (int nt = 0; nt < 4; nt++)
            #pragma unroll
            for (int r = 0; r < 4; r++) { accg[mt][nt][r] = 0.f; accu[mt][nt][r] = 0.f; }

    // ---- prologue: chunk 0 -> stage 0 ----
    float4 ra0 = *(const float4*)(aptr[0]);
    float4 ra1 = *(const float4*)(aptr[1]);
    float4 rb0 = *(const float4*)(bp);
    float4 rb1 = *(const float4*)(bp + (size_t)8 * idim);
    {
        unsigned h0, l0, h1, l1;
        split2(ra0.x, ra0.y, h0, l0); split2(ra0.z, ra0.w, h1, l1);
        *(uint2*)&Ah[0][mA[0] * A_STR + kA[0]] = make_uint2(h0, h1);
        *(uint2*)&Al[0][mA[0] * A_STR + kA[0]] = make_uint2(l0, l1);
        split2(ra1.x, ra1.y, h0, l0); split2(ra1.z, ra1.w, h1, l1);
        *(uint2*)&Ah[0][mA[1] * A_STR + kA[1]] = make_uint2(h0, h1);
        *(uint2*)&Al[0][mA[1] * A_STR + kA[1]] = make_uint2(l0, l1);
        split2(rb0.x, rb0.y, h0, l0); split2(rb0.z, rb0.w, h1, l1);
        *(uint2*)&BH0[kr * B_STR + nq] = make_uint2(h0, h1);
        *(uint2*)&BL0[kr * B_STR + nq] = make_uint2(l0, l1);
        split2(rb1.x, rb1.y, h0, l0); split2(rb1.z, rb1.w, h1, l1);
        *(uint2*)&BH0[(kr + 8) * B_STR + nq] = make_uint2(h0, h1);
        *(uint2*)&BL0[(kr + 8) * B_STR + nq] = make_uint2(l0, l1);
    }
    __syncthreads();

    const int NCH = ND / 16;
    for (int c = 0; c < NCH; c++) {
        int p = c & 1;
        bool more = (c + 1 < NCH);
        if (more) {
            int kt = (c + 1) * 16;
            ra0 = *(const float4*)(aptr[0] + kt);
            ra1 = *(const float4*)(aptr[1] + kt);
            rb0 = *(const float4*)(bp + (size_t)kt * idim);
            rb1 = *(const float4*)(bp + (size_t)(kt + 8) * idim);
        }
        {
            uint32_t ao = p * A_SZB, bo = p * B_SZB;
            unsigned ah[2][4], al[2][4];
            ldsm4(ah[0], a_ld_h[0] + ao); ldsm4(ah[1], a_ld_h[1] + ao);
            ldsm4(al[0], a_ld_l[0] + ao); ldsm4(al[1], a_ld_l[1] + ao);
            #pragma unroll
            for (int np = 0; np < 2; np++) {
                unsigned bgh[4], bgl[4], buh[4], bul[4];
                ldsm4t(bgh, b_ld[0][np] + bo); ldsm4t(bgl, b_ld[1][np] + bo);
                ldsm4t(buh, b_ld[2][np] + bo); ldsm4t(bul, b_ld[3][np] + bo);
                #pragma unroll
                for (int j = 0; j < 2; j++) {
                    int nt = np * 2 + j;
                    #pragma unroll
                    for (int mt = 0; mt < 2; mt++) {
                        mma_bf16(accg[mt][nt], ah[mt], &bgh[2 * j]);
                        mma_bf16(accg[mt][nt], al[mt], &bgh[2 * j]);
                        mma_bf16(accg[mt][nt], ah[mt], &bgl[2 * j]);
                        mma_bf16(accu[mt][nt], ah[mt], &buh[2 * j]);
                        mma_bf16(accu[mt][nt], al[mt], &buh[2 * j]);
                        mma_bf16(accu[mt][nt], ah[mt], &bul[2 * j]);
                    }
                }
            }
        }
        if (more) {
            int q = p ^ 1;
            unsigned short* BHq = mat ? Buh[q] : Bgh[q];
            unsigned short* BLq = mat ? Bul[q] : Bgl[q];
            unsigned h0, l0, h1, l1;
            split2(ra0.x, ra0.y, h0, l0); split2(ra0.z, ra0.w, h1, l1);
            *(uint2*)&Ah[q][mA[0] * A_STR + kA[0]] = make_uint2(h0, h1);
            *(uint2*)&Al[q][mA[0] * A_STR + kA[0]] = make_uint2(l0, l1);
            split2(ra1.x, ra1.y, h0, l0); split2(ra1.z, ra1.w, h1, l1);
            *(uint2*)&Ah[q][mA[1] * A_STR + kA[1]] = make_uint2(h0, h1);
            *(uint2*)&Al[q][mA[1] * A_STR + kA[1]] = make_uint2(l0, l1);
            split2(rb0.x, rb0.y, h0, l0); split2(rb0.z, rb0.w, h1, l1);
            *(uint2*)&BHq[kr * B_STR + nq] = make_uint2(h0, h1);
            *(uint2*)&BLq[kr * B_STR + nq] = make_uint2(l0, l1);
            split2(rb1.x, rb1.y, h0, l0); split2(rb1.z, rb1.w, h1, l1);
            *(uint2*)&BHq[(kr + 8) * B_STR + nq] = make_uint2(h0, h1);
            *(uint2*)&BLq[(kr + 8) * B_STR + nq] = make_uint2(l0, l1);
        }
        __syncthreads();
    }

    // epilogue: silu(gate) * up -> fp32 H
    #pragma unroll
    for (int mt = 0; mt < 2; mt++) {
        #pragma unroll
        for (int half = 0; half < 2; half++) {
            int r = m0 + warpM * 32 + mt * 16 + half * 8 + gq;
            if (r >= cnt) continue;
            float* hrow = H + (size_t)(off + r) * idim + n0 + warpN * 32;
            #pragma unroll
            for (int nt = 0; nt < 4; nt++) {
                float gv0 = accg[mt][nt][half * 2 + 0];
                float gv1 = accg[mt][nt][half * 2 + 1];
                float uv0 = accu[mt][nt][half * 2 + 0];
                float uv1 = accu[mt][nt][half * 2 + 1];
                float2 hv;
                hv.x = gv0 / (1.f + expf(-gv0)) * uv0;
                hv.y = gv1 / (1.f + expf(-gv1)) * uv1;
                *(float2*)&hrow[nt * 8 + 2 * tq] = hv;
            }
        }
    }
}

// ---------------- GEMM 2: out += (routed: 2.5*w) H @ Wd  (out pre-zeroed) ----
__global__ void __launch_bounds__(256, 2)
gemm_down_all(const float* __restrict__ Wd, const float* __restrict__ SWd,
              float* __restrict__ out) {
    int z = blockIdx.z;
    bool shared_e = (z == NE);
    int cnt, off, idim;
    const float* wd;
    const float* Hsrc;
    if (shared_e) {
        cnt = NT; off = 0; idim = NSI;
        wd = SWd; Hsrc = g_hs;
    } else {
        cnt = g_counts[z]; off = g_offsets[z]; idim = NI;
        wd = Wd + (size_t)z * NI * ND;
        Hsrc = g_h;
    }
    int m0 = blockIdx.x * 128;
    if (m0 >= cnt) return;
    int n0 = blockIdx.y * 64;

    __shared__ __align__(16) unsigned short Ah[2][A_SZ], Al[2][A_SZ];
    __shared__ __align__(16) unsigned short Bh[2][B_SZ], Bl[2][B_SZ];

    int tid  = threadIdx.x;
    int lane = tid & 31, wid = tid >> 5;
    int warpM = wid >> 1, warpN = wid & 1;
    int gq = lane >> 2, tq = lane & 3;

    const float* aptr[2]; int mA[2], kA[2];
    #pragma unroll
    for (int l = 0; l < 2; l++) {
        int idx = tid + l * 256;
        mA[l] = idx >> 2; kA[l] = (idx & 3) << 2;
        int m = m0 + mA[l];
        int hr = (m < cnt) ? (off + m) : off;
        aptr[l] = Hsrc + (size_t)hr * idim + kA[l];
    }
    int kr = tid >> 4, nq = (tid & 15) << 2;
    const float* bp = wd + (size_t)kr * ND + n0 + nq;

    int arow = lane & 15, acolb = (lane >> 4) << 4;
    uint32_t a_ld_h[2], a_ld_l[2];
    #pragma unroll
    for (int mt = 0; mt < 2; mt++) {
        int r = warpM * 32 + mt * 16 + arow;
        a_ld_h[mt] = sptr(Ah) + r * (A_STR * 2) + acolb;
        a_ld_l[mt] = sptr(Al) + r * (A_STR * 2) + acolb;
    }
    int bkr = lane & 15;
    int bcolb = (warpN * 32) * 2 + ((lane >> 4) << 4);
    uint32_t b_ld_h[2], b_ld_l[2];
    #pragma unroll
    for (int np = 0; np < 2; np++) {
        b_ld_h[np] = sptr(Bh) + bkr * (B_STR * 2) + bcolb + np * 32;
        b_ld_l[np] = sptr(Bl) + bkr * (B_STR * 2) + bcolb + np * 32;
    }

    float acc[2][4][4];
    #pragma unroll
    for (int mt = 0; mt < 2; mt++)
        #pragma unroll
        for (int nt = 0; nt < 4; nt++)
            #pragma unroll
            for (int r = 0; r < 4; r++) acc[mt][nt][r] = 0.f;

    float4 ra0 = *(const float4*)(aptr[0]);
    float4 ra1 = *(const float4*)(aptr[1]);
    float4 rb  = *(const float4*)(bp);
    {
        unsigned h0, l0, h1, l1;
        split2(ra0.x, ra0.y, h0, l0); split2(ra0.z, ra0.w, h1, l1);
        *(uint2*)&Ah[0][mA[0] * A_STR + kA[0]] = make_uint2(h0, h1);
        *(uint2*)&Al[0][mA[0] * A_STR + kA[0]] = make_uint2(l0, l1);
        split2(ra1.x, ra1.y, h0, l0); split2(ra1.z, ra1.w, h1, l1);
        *(uint2*)&Ah[0][mA[1] * A_STR + kA[1]] = make_uint2(h0, h1);
        *(uint2*)&Al[0][mA[1] * A_STR + kA[1]] = make_uint2(l0, l1);
        split2(rb.x, rb.y, h0, l0); split2(rb.z, rb.w, h1, l1);
        *(uint2*)&Bh[0][kr * B_STR + nq] = make_uint2(h0, h1);
        *(uint2*)&Bl[0][kr * B_STR + nq] = make_uint2(l0, l1);
    }
    __syncthreads();

    const int NCH = idim / 16;
    for (int c = 0; c < NCH; c++) {
        int p = c & 1;
        bool more = (c + 1 < NCH);
        if (more) {
            int kt = (c + 1) * 16;
            ra0 = *(const float4*)(aptr[0] + kt);
            ra1 = *(const float4*)(aptr[1] + kt);
            rb  = *(const float4*)(bp + (size_t)kt * ND);
        }
        {
            uint32_t ao = p * A_SZB, bo = p * B_SZB;
            unsigned ah[2][4], al[2][4];
            ldsm4(ah[0], a_ld_h[0] + ao); ldsm4(ah[1], a_ld_h[1] + ao);
            ldsm4(al[0], a_ld_l[0] + ao); ldsm4(al[1], a_ld_l[1] + ao);
            #pragma unroll
            for (int np = 0; np < 2; np++) {
                unsigned bh[4], bl[4];
                ldsm4t(bh, b_ld_h[np] + bo); ldsm4t(bl, b_ld_l[np] + bo);
                #pragma unroll
                for (int j = 0; j < 2; j++) {
                    int nt = np * 2 + j;
                    #pragma unroll
                    for (int mt = 0; mt < 2; mt++) {
                        mma_bf16(acc[mt][nt], ah[mt], &bh[2 * j]);
                        mma_bf16(acc[mt][nt], al[mt], &bh[2 * j]);
                        mma_bf16(acc[mt][nt], ah[mt], &bl[2 * j]);
                    }
                }
            }
        }
        if (more) {
            int q = p ^ 1;
            unsigned h0, l0, h1, l1;
            split2(ra0.x, ra0.y, h0, l0); split2(ra0.z, ra0.w, h1, l1);
            *(uint2*)&Ah[q][mA[0] * A_STR + kA[0]] = make_uint2(h0, h1);
            *(uint2*)&Al[q][mA[0] * A_STR + kA[0]] = make_uint2(l0, l1);
            split2(ra1.x, ra1.y, h0, l0); split2(ra1.z, ra1.w, h1, l1);
            *(uint2*)&Ah[q][mA[1] * A_STR + kA[1]] = make_uint2(h0, h1);
            *(uint2*)&Al[q][mA[1] * A_STR + kA[1]] = make_uint2(l0, l1);
            split2(rb.x, rb.y, h0, l0); split2(rb.z, rb.w, h1, l1);
            *(uint2*)&Bh[q][kr * B_STR + nq] = make_uint2(h0, h1);
            *(uint2*)&Bl[q][kr * B_STR + nq] = make_uint2(l0, l1);
        }
        __syncthreads();
    }

    // epilogue: atomic accumulate (out pre-zeroed by memset)
    #pragma unroll
    for (int mt = 0; mt < 2; mt++) {
        #pragma unroll
        for (int half = 0; half < 2; half++) {
            int r = m0 + warpM * 32 + mt * 16 + half * 8 + gq;
            if (r >= cnt) continue;
            int tok; float w;
            if (shared_e) { tok = r; w = 1.0f; }
            else {
                int grow = off + r;
                tok = g_rowlist[grow];
                w   = g_roww[grow] * 2.5f;
            }
            float* op = out + (size_t)tok * ND + n0 + warpN * 32;
            #pragma unroll
            for (int nt = 0; nt < 4; nt++) {
                atomicAdd(&op[nt * 8 + 2 * tq],     w * acc[mt][nt][half * 2 + 0]);
                atomicAdd(&op[nt * 8 + 2 * tq + 1], w * acc[mt][nt][half * 2 + 1]);
            }
        }
    }
}

// ---------------- launch ----------------
extern "C" void kernel_launch(void* const* d_in, const int* in_sizes, int n_in,
                              void* d_out, int out_size) {
    const float* x       = (const float*)d_in[0];
    const float* gate_w  = (const float*)d_in[1];
    const float* gate_b  = (const float*)d_in[2];
    const float* w_gate  = (const float*)d_in[3];
    const float* w_up    = (const float*)d_in[4];
    const float* w_down  = (const float*)d_in[5];
    const float* sw_gate = (const float*)d_in[6];
    const float* sw_up   = (const float*)d_in[7];
    const float* sw_down = (const float*)d_in[8];
    float* out = (float*)d_out;

    zero_kernel   <<<1, 32>>>();
    gate_kernel   <<<NT, 256>>>(x, gate_w, gate_b);
    scan_kernel   <<<1, 32>>>();
    scatter_kernel<<<NA / 256, 256>>>();

    // gated: routed experts (z<32, 22 n-blocks) + shared expert (z==32, 44 n-blocks)
    gemm_gated_all<<<dim3(NT / 128, NSI / 64, NE + 1), 256>>>(
        x, w_gate, w_up, sw_gate, sw_up);

    // down: out zero-init, then everyone atomically accumulates
    cudaMemsetAsync(out, 0, (size_t)out_size * sizeof(float));
    gemm_down_all<<<dim3(NT / 128, ND / 64, NE + 1), 256>>>(
        w_down, sw_down, out);
}

// round 14
// speedup vs baseline: 1.0778x; 1.0205x over previous
#include <cuda_runtime.h>
#include <math.h>
#include <stdint.h>

// Problem constants
#define NT   1024          // tokens
#define ND   2048          // hidden dim
#define NE   32            // experts
#define NI   1408          // routed intermediate
#define NSI  2816          // shared intermediate
#define NG   8             // groups
#define EPG  4             // experts per group
#define NA   (NT * 4)      // total assignments (top_k = 4)

// ---------------- device scratch ----------------
__device__ float g_h [NA * NI];    // routed  silu(x@Wg)*(x@Wu)  (fp32)
__device__ float g_hs[NT * NSI];   // shared  silu(x@Sg)*(x@Su)
__device__ int   g_rowlist[NA];
__device__ float g_roww  [NA];
__device__ int   g_counts [NE];
__device__ int   g_offsets[NE];
__device__ int   g_tid4[NA];
__device__ float g_tw4 [NA];

// ---------------- bf16 split + mma helpers ----------------
__device__ __forceinline__ void split2(float v0, float v1, unsigned& h, unsigned& l) {
    unsigned hh;
    asm("cvt.rn.bf16x2.f32 %0, %1, %2;" : "=r"(hh) : "f"(v1), "f"(v0));
    float h0 = __uint_as_float(hh << 16);
    float h1 = __uint_as_float(hh & 0xffff0000u);
    asm("cvt.rn.bf16x2.f32 %0, %1, %2;" : "=r"(l) : "f"(v1 - h1), "f"(v0 - h0));
    h = hh;
}

__device__ __forceinline__ void mma_bf16(float* d, const unsigned* a, const unsigned* b) {
    asm volatile(
        "mma.sync.aligned.m16n8k16.row.col.f32.bf16.bf16.f32 "
        "{%0,%1,%2,%3}, {%4,%5,%6,%7}, {%8,%9}, {%0,%1,%2,%3};"
        : "+f"(d[0]), "+f"(d[1]), "+f"(d[2]), "+f"(d[3])
        : "r"(a[0]), "r"(a[1]), "r"(a[2]), "r"(a[3]), "r"(b[0]), "r"(b[1]));
}

__device__ __forceinline__ void ldsm4(unsigned* r, uint32_t a) {
    asm volatile("ldmatrix.sync.aligned.m8n8.x4.shared.b16 {%0,%1,%2,%3}, [%4];"
        : "=r"(r[0]), "=r"(r[1]), "=r"(r[2]), "=r"(r[3]) : "r"(a));
}
__device__ __forceinline__ void ldsm4t(unsigned* r, uint32_t a) {
    asm volatile("ldmatrix.sync.aligned.m8n8.x4.trans.shared.b16 {%0,%1,%2,%3}, [%4];"
        : "=r"(r[0]), "=r"(r[1]), "=r"(r[2]), "=r"(r[3]) : "r"(a));
}
__device__ __forceinline__ uint32_t sptr(const void* p) {
    return (uint32_t)__cvta_generic_to_shared(p);
}

// ---------------- routing kernels ----------------
// gate: logits -> sigmoid -> biased grouped top-4 (per token). No global atomics.
__global__ void gate_kernel(const float* __restrict__ x,
                            const float* __restrict__ gw,
                            const float* __restrict__ gb) {
    __shared__ float xs[ND];
    __shared__ float logit[NE];
    int t = blockIdx.x;
    for (int k = threadIdx.x; k < ND; k += 256) xs[k] = x[(size_t)t * ND + k];
    __syncthreads();
    int e = threadIdx.x >> 3;
    int j = threadIdx.x & 7;
    const float* w = gw + (size_t)e * ND;
    float s = 0.f;
    for (int k = j; k < ND; k += 8) s += xs[k] * w[k];
    s += __shfl_xor_sync(0xffffffffu, s, 1);
    s += __shfl_xor_sync(0xffffffffu, s, 2);
    s += __shfl_xor_sync(0xffffffffu, s, 4);
    if (j == 0) logit[e] = s + gb[e];
    __syncthreads();
    if (threadIdx.x == 0) {
        float sc[NE], scb[NE];
        #pragma unroll
        for (int i = 0; i < NE; i++) {
            float v = 1.f / (1.f + expf(-logit[i]));
            sc[i]  = v;
            scb[i] = v + gb[i];
        }
        float gs[NG];
        #pragma unroll
        for (int g = 0; g < NG; g++) {
            float m1 = -1e30f, m2 = -1e30f;
            #pragma unroll
            for (int q = 0; q < EPG; q++) {
                float v = scb[g * EPG + q];
                if (v > m1) { m2 = m1; m1 = v; } else if (v > m2) { m2 = v; }
            }
            gs[g] = m1 + m2;
        }
        bool gsel[NG];
        #pragma unroll
        for (int g = 0; g < NG; g++) gsel[g] = false;
        for (int r = 0; r < 4; r++) {
            float best = -1e30f; int bi = 0;
            for (int g = 0; g < NG; g++)
                if (!gsel[g] && gs[g] > best) { best = gs[g]; bi = g; }
            gsel[bi] = true;
        }
        float tmp[NE];
        #pragma unroll
        for (int i = 0; i < NE; i++) tmp[i] = gsel[i / EPG] ? scb[i] : 0.0f;
        int ids[4]; float tw[4]; float wsum = 0.f;
        for (int r = 0; r < 4; r++) {
            float best = -1e30f; int bi = 0;
            for (int i = 0; i < NE; i++)
                if (tmp[i] > best) { best = tmp[i]; bi = i; }
            tmp[bi] = -1e30f;
            ids[r] = bi;
            tw[r] = sc[bi];
            wsum += tw[r];
        }
        float inv = 1.f / wsum;
        for (int r = 0; r < 4; r++) {
            g_tid4[t * 4 + r] = ids[r];
            g_tw4 [t * 4 + r] = tw[r] * inv;
        }
    }
}

// fused count + scan + scatter, single block of 1024 threads
__global__ void route_kernel() {
    __shared__ int cnts[NE];
    __shared__ int curs[NE];
    int tid = threadIdx.x;
    if (tid < NE) cnts[tid] = 0;
    __syncthreads();
    for (int i = tid; i < NA; i += 1024)
        atomicAdd(&cnts[g_tid4[i]], 1);
    __syncthreads();
    if (tid < 32) {
        int c = cnts[tid];
        int v = c;
        #pragma unroll
        for (int o = 1; o < 32; o <<= 1) {
            int u = __shfl_up_sync(0xffffffffu, v, o);
            if (tid >= o) v += u;
        }
        g_counts[tid]  = c;
        g_offsets[tid] = v - c;
        curs[tid]      = v - c;
    }
    __syncthreads();
    for (int i = tid; i < NA; i += 1024) {
        int e = g_tid4[i];
        int pos = atomicAdd(&curs[e], 1);
        g_rowlist[pos] = i >> 2;
        g_roww[pos]    = g_tw4[i];
    }
}

// ============================================================================
// bf16x3 mma.sync GEMMs, LDSM fragments, 2-stage ping-pong.
// Gated grid (8, 22, 34): z=0,1 shared-expert n-slices (NSI), z>=2 routed
// expert z-2 (NI). No dead n-blocks; uniform K=2048; shared dispatched first.
// Down grid (8, 32, 34): z=0,1 shared-expert K-halves (each 1408 of NSI),
// z>=2 routed expert z-2 (K=NI=1408). All blocks exactly 88 chunks.
// Block BM=128, BN=64, BK=16; 256 thr = 8 warps (4M x 2N); warp tile 32x32.
// ============================================================================

#define A_STR 24
#define B_STR 72
#define A_SZ  (128 * A_STR)
#define B_SZ  (16 * B_STR)
#define A_SZB (A_SZ * 2)
#define B_SZB (B_SZ * 2)

// ---------------- GEMM 1: H = silu(A@Wg) * (A@Wu) ----------------
__global__ void __launch_bounds__(256, 2)
gemm_gated_all(const float* __restrict__ x,
               const float* __restrict__ Wg,  const float* __restrict__ Wu,
               const float* __restrict__ SWg, const float* __restrict__ SWu) {
    int z = blockIdx.z;
    bool shared_e = (z < 2);
    int cnt, off, idim, n0;
    const float* wg;
    const float* wu;
    float* H;
    if (shared_e) {
        cnt = NT; off = 0; idim = NSI;
        wg = SWg; wu = SWu; H = g_hs;
        n0 = (z * 22 + blockIdx.y) * 64;
    } else {
        int e = z - 2;
        cnt = g_counts[e]; off = g_offsets[e]; idim = NI;
        wg = Wg + (size_t)e * ND * NI;
        wu = Wu + (size_t)e * ND * NI;
        H = g_h;
        n0 = blockIdx.y * 64;
    }
    int m0 = blockIdx.x * 128;
    if (m0 >= cnt) return;

    __shared__ __align__(16) unsigned short Ah[2][A_SZ], Al[2][A_SZ];
    __shared__ __align__(16) unsigned short Bgh[2][B_SZ], Bgl[2][B_SZ];
    __shared__ __align__(16) unsigned short Buh[2][B_SZ], Bul[2][B_SZ];

    int tid  = threadIdx.x;
    int lane = tid & 31, wid = tid >> 5;
    int warpM = wid >> 1, warpN = wid & 1;
    int gq = lane >> 2, tq = lane & 3;

    // ---- A staging: 2 float4 per thread over 128x16 fp32 ----
    const float* aptr[2]; int mA[2], kA[2];
    #pragma unroll
    for (int l = 0; l < 2; l++) {
        int idx = tid + l * 256;
        mA[l] = idx >> 2; kA[l] = (idx & 3) << 2;
        int m = m0 + mA[l];
        int tok;
        if (shared_e) tok = (m < cnt) ? m : 0;
        else          tok = (m < cnt) ? g_rowlist[off + m] : 0;
        aptr[l] = x + (size_t)tok * ND + kA[l];
    }
    // ---- B staging: 2 matrices x 128 threads; rows kr, kr+8; 4 n-vals ----
    int mat = tid >> 7, rr = tid & 127;
    int kr  = rr >> 4, nq = (rr & 15) << 2;
    const float* bp = (mat ? wu : wg) + (size_t)kr * idim + n0 + nq;
    unsigned short* BH0 = mat ? Buh[0] : Bgh[0];
    unsigned short* BL0 = mat ? Bul[0] : Bgl[0];

    // ---- LDSM base addresses ----
    int arow = lane & 15, acolb = (lane >> 4) << 4;
    uint32_t a_ld_h[2], a_ld_l[2];
    #pragma unroll
    for (int mt = 0; mt < 2; mt++) {
        int r = warpM * 32 + mt * 16 + arow;
        a_ld_h[mt] = sptr(Ah) + r * (A_STR * 2) + acolb;
        a_ld_l[mt] = sptr(Al) + r * (A_STR * 2) + acolb;
    }
    int bkr = lane & 15;
    int bcolb = (warpN * 32) * 2 + ((lane >> 4) << 4);
    uint32_t b_ld[4][2];
    const void* barr[4] = {Bgh, Bgl, Buh, Bul};
    #pragma unroll
    for (int a = 0; a < 4; a++)
        #pragma unroll
        for (int np = 0; np < 2; np++)
            b_ld[a][np] = sptr(barr[a]) + bkr * (B_STR * 2) + bcolb + np * 32;

    float accg[2][4][4], accu[2][4][4];
    #pragma unroll
    for (int mt = 0; mt < 2; mt++)
        #pragma unroll
        for (int nt = 0; nt < 4; nt++)
            #pragma unroll
            for (int r = 0; r < 4; r++) { accg[mt][nt][r] = 0.f; accu[mt][nt][r] = 0.f; }

    // ---- prologue: chunk 0 -> stage 0 ----
    float4 ra0 = *(const float4*)(aptr[0]);
    float4 ra1 = *(const float4*)(aptr[1]);
    float4 rb0 = *(const float4*)(bp);
    float4 rb1 = *(const float4*)(bp + (size_t)8 * idim);
    {
        unsigned h0, l0, h1, l1;
        split2(ra0.x, ra0.y, h0, l0); split2(ra0.z, ra0.w, h1, l1);
        *(uint2*)&Ah[0][mA[0] * A_STR + kA[0]] = make_uint2(h0, h1);
        *(uint2*)&Al[0][mA[0] * A_STR + kA[0]] = make_uint2(l0, l1);
        split2(ra1.x, ra1.y, h0, l0); split2(ra1.z, ra1.w, h1, l1);
        *(uint2*)&Ah[0][mA[1] * A_STR + kA[1]] = make_uint2(h0, h1);
        *(uint2*)&Al[0][mA[1] * A_STR + kA[1]] = make_uint2(l0, l1);
        split2(rb0.x, rb0.y, h0, l0); split2(rb0.z, rb0.w, h1, l1);
        *(uint2*)&BH0[kr * B_STR + nq] = make_uint2(h0, h1);
        *(uint2*)&BL0[kr * B_STR + nq] = make_uint2(l0, l1);
        split2(rb1.x, rb1.y, h0, l0); split2(rb1.z, rb1.w, h1, l1);
        *(uint2*)&BH0[(kr + 8) * B_STR + nq] = make_uint2(h0, h1);
        *(uint2*)&BL0[(kr + 8) * B_STR + nq] = make_uint2(l0, l1);
    }
    __syncthreads();

    const int NCH = ND / 16;
    for (int c = 0; c < NCH; c++) {
        int p = c & 1;
        bool more = (c + 1 < NCH);
        if (more) {
            int kt = (c + 1) * 16;
            ra0 = *(const float4*)(aptr[0] + kt);
            ra1 = *(const float4*)(aptr[1] + kt);
            rb0 = *(const float4*)(bp + (size_t)kt * idim);
            rb1 = *(const float4*)(bp + (size_t)(kt + 8) * idim);
        }
        {
            uint32_t ao = p * A_SZB, bo = p * B_SZB;
            unsigned ah[2][4], al[2][4];
            ldsm4(ah[0], a_ld_h[0] + ao); ldsm4(ah[1], a_ld_h[1] + ao);
            ldsm4(al[0], a_ld_l[0] + ao); ldsm4(al[1], a_ld_l[1] + ao);
            #pragma unroll
            for (int np = 0; np < 2; np++) {
                unsigned bgh[4], bgl[4], buh[4], bul[4];
                ldsm4t(bgh, b_ld[0][np] + bo); ldsm4t(bgl, b_ld[1][np] + bo);
                ldsm4t(buh, b_ld[2][np] + bo); ldsm4t(bul, b_ld[3][np] + bo);
                #pragma unroll
                for (int j = 0; j < 2; j++) {
                    int nt = np * 2 + j;
                    #pragma unroll
                    for (int mt = 0; mt < 2; mt++) {
                        mma_bf16(accg[mt][nt], ah[mt], &bgh[2 * j]);
                        mma_bf16(accg[mt][nt], al[mt], &bgh[2 * j]);
                        mma_bf16(accg[mt][nt], ah[mt], &bgl[2 * j]);
                        mma_bf16(accu[mt][nt], ah[mt], &buh[2 * j]);
                        mma_bf16(accu[mt][nt], al[mt], &buh[2 * j]);
                        mma_bf16(accu[mt][nt], ah[mt], &bul[2 * j]);
                    }
                }
            }
        }
        if (more) {
            int q = p ^ 1;
            unsigned short* BHq = mat ? Buh[q] : Bgh[q];
            unsigned short* BLq = mat ? Bul[q] : Bgl[q];
            unsigned h0, l0, h1, l1;
            split2(ra0.x, ra0.y, h0, l0); split2(ra0.z, ra0.w, h1, l1);
            *(uint2*)&Ah[q][mA[0] * A_STR + kA[0]] = make_uint2(h0, h1);
            *(uint2*)&Al[q][mA[0] * A_STR + kA[0]] = make_uint2(l0, l1);
            split2(ra1.x, ra1.y, h0, l0); split2(ra1.z, ra1.w, h1, l1);
            *(uint2*)&Ah[q][mA[1] * A_STR + kA[1]] = make_uint2(h0, h1);
            *(uint2*)&Al[q][mA[1] * A_STR + kA[1]] = make_uint2(l0, l1);
            split2(rb0.x, rb0.y, h0, l0); split2(rb0.z, rb0.w, h1, l1);
            *(uint2*)&BHq[kr * B_STR + nq] = make_uint2(h0, h1);
            *(uint2*)&BLq[kr * B_STR + nq] = make_uint2(l0, l1);
            split2(rb1.x, rb1.y, h0, l0); split2(rb1.z, rb1.w, h1, l1);
            *(uint2*)&BHq[(kr + 8) * B_STR + nq] = make_uint2(h0, h1);
            *(uint2*)&BLq[(kr + 8) * B_STR + nq] = make_uint2(l0, l1);
        }
        __syncthreads();
    }

    // epilogue: silu(gate) * up -> fp32 H
    #pragma unroll
    for (int mt = 0; mt < 2; mt++) {
        #pragma unroll
        for (int half = 0; half < 2; half++) {
            int r = m0 + warpM * 32 + mt * 16 + half * 8 + gq;
            if (r >= cnt) continue;
            float* hrow = H + (size_t)(off + r) * idim + n0 + warpN * 32;
            #pragma unroll
            for (int nt = 0; nt < 4; nt++) {
                float gv0 = accg[mt][nt][half * 2 + 0];
                float gv1 = accg[mt][nt][half * 2 + 1];
                float uv0 = accu[mt][nt][half * 2 + 0];
                float uv1 = accu[mt][nt][half * 2 + 1];
                float2 hv;
                hv.x = gv0 / (1.f + expf(-gv0)) * uv0;
                hv.y = gv1 / (1.f + expf(-gv1)) * uv1;
                *(float2*)&hrow[nt * 8 + 2 * tq] = hv;
            }
        }
    }
}

// ---------------- GEMM 2: out += w * H @ Wd  (out pre-zeroed; all atomic) ----
__global__ void __launch_bounds__(256, 2)
gemm_down_all(const float* __restrict__ Wd, const float* __restrict__ SWd,
              float* __restrict__ out) {
    int z = blockIdx.z;
    bool shared_e = (z < 2);
    int cnt, off, astride, kbase;
    const float* wd;
    const float* Hsrc;
    if (shared_e) {
        cnt = NT; off = 0; astride = NSI; kbase = z * NI;  // K-half of NSI
        wd = SWd + (size_t)kbase * ND;
        Hsrc = g_hs;
    } else {
        int e = z - 2;
        cnt = g_counts[e]; off = g_offsets[e]; astride = NI; kbase = 0;
        wd = Wd + (size_t)e * NI * ND;
        Hsrc = g_h;
    }
    int m0 = blockIdx.x * 128;
    if (m0 >= cnt) return;
    int n0 = blockIdx.y * 64;

    __shared__ __align__(16) unsigned short Ah[2][A_SZ], Al[2][A_SZ];
    __shared__ __align__(16) unsigned short Bh[2][B_SZ], Bl[2][B_SZ];

    int tid  = threadIdx.x;
    int lane = tid & 31, wid = tid >> 5;
    int warpM = wid >> 1, warpN = wid & 1;
    int gq = lane >> 2, tq = lane & 3;

    const float* aptr[2]; int mA[2], kA[2];
    #pragma unroll
    for (int l = 0; l < 2; l++) {
        int idx = tid + l * 256;
        mA[l] = idx >> 2; kA[l] = (idx & 3) << 2;
        int m = m0 + mA[l];
        int hr = (m < cnt) ? (off + m) : off;
        aptr[l] = Hsrc + (size_t)hr * astride + kbase + kA[l];
    }
    int kr = tid >> 4, nq = (tid & 15) << 2;
    const float* bp = wd + (size_t)kr * ND + n0 + nq;

    int arow = lane & 15, acolb = (lane >> 4) << 4;
    uint32_t a_ld_h[2], a_ld_l[2];
    #pragma unroll
    for (int mt = 0; mt < 2; mt++) {
        int r = warpM * 32 + mt * 16 + arow;
        a_ld_h[mt] = sptr(Ah) + r * (A_STR * 2) + acolb;
        a_ld_l[mt] = sptr(Al) + r * (A_STR * 2) + acolb;
    }
    int bkr = lane & 15;
    int bcolb = (warpN * 32) * 2 + ((lane >> 4) << 4);
    uint32_t b_ld_h[2], b_ld_l[2];
    #pragma unroll
    for (int np = 0; np < 2; np++) {
        b_ld_h[np] = sptr(Bh) + bkr * (B_STR * 2) + bcolb + np * 32;
        b_ld_l[np] = sptr(Bl) + bkr * (B_STR * 2) + bcolb + np * 32;
    }

    float acc[2][4][4];
    #pragma unroll
    for (int mt = 0; mt < 2; mt++)
        #pragma unroll
        for (int nt = 0; nt < 4; nt++)
            #pragma unroll
            for (int r = 0; r < 4; r++) acc[mt][nt][r] = 0.f;

    float4 ra0 = *(const float4*)(aptr[0]);
    float4 ra1 = *(const float4*)(aptr[1]);
    float4 rb  = *(const float4*)(bp);
    {
        unsigned h0, l0, h1, l1;
        split2(ra0.x, ra0.y, h0, l0); split2(ra0.z, ra0.w, h1, l1);
        *(uint2*)&Ah[0][mA[0] * A_STR + kA[0]] = make_uint2(h0, h1);
        *(uint2*)&Al[0][mA[0] * A_STR + kA[0]] = make_uint2(l0, l1);
        split2(ra1.x, ra1.y, h0, l0); split2(ra1.z, ra1.w, h1, l1);
        *(uint2*)&Ah[0][mA[1] * A_STR + kA[1]] = make_uint2(h0, h1);
        *(uint2*)&Al[0][mA[1] * A_STR + kA[1]] = make_uint2(l0, l1);
        split2(rb.x, rb.y, h0, l0); split2(rb.z, rb.w, h1, l1);
        *(uint2*)&Bh[0][kr * B_STR + nq] = make_uint2(h0, h1);
        *(uint2*)&Bl[0][kr * B_STR + nq] = make_uint2(l0, l1);
    }
    __syncthreads();

    const int NCH = NI / 16;   // 88 chunks for ALL blocks (uniform duration)
    for (int c = 0; c < NCH; c++) {
        int p = c & 1;
        bool more = (c + 1 < NCH);
        if (more) {
            int kt = (c + 1) * 16;
            ra0 = *(const float4*)(aptr[0] + kt);
            ra1 = *(const float4*)(aptr[1] + kt);
            rb  = *(const float4*)(bp + (size_t)kt * ND);
        }
        {
            uint32_t ao = p * A_SZB, bo = p * B_SZB;
            unsigned ah[2][4], al[2][4];
            ldsm4(ah[0], a_ld_h[0] + ao); ldsm4(ah[1], a_ld_h[1] + ao);
            ldsm4(al[0], a_ld_l[0] + ao); ldsm4(al[1], a_ld_l[1] + ao);
            #pragma unroll
            for (int np = 0; np < 2; np++) {
                unsigned bh[4], bl[4];
                ldsm4t(bh, b_ld_h[np] + bo); ldsm4t(bl, b_ld_l[np] + bo);
                #pragma unroll
                for (int j = 0; j < 2; j++) {
                    int nt = np * 2 + j;
                    #pragma unroll
                    for (int mt = 0; mt < 2; mt++) {
                        mma_bf16(acc[mt][nt], ah[mt], &bh[2 * j]);
                        mma_bf16(acc[mt][nt], al[mt], &bh[2 * j]);
                        mma_bf16(acc[mt][nt], ah[mt], &bl[2 * j]);
                    }
                }
            }
        }
        if (more) {
            int q = p ^ 1;
            unsigned h0, l0, h1, l1;
            split2(ra0.x, ra0.y, h0, l0); split2(ra0.z, ra0.w, h1, l1);
            *(uint2*)&Ah[q][mA[0] * A_STR + kA[0]] = make_uint2(h0, h1);
            *(uint2*)&Al[q][mA[0] * A_STR + kA[0]] = make_uint2(l0, l1);
            split2(ra1.x, ra1.y, h0, l0); split2(ra1.z, ra1.w, h1, l1);
            *(uint2*)&Ah[q][mA[1] * A_STR + kA[1]] = make_uint2(h0, h1);
            *(uint2*)&Al[q][mA[1] * A_STR + kA[1]] = make_uint2(l0, l1);
            split2(rb.x, rb.y, h0, l0); split2(rb.z, rb.w, h1, l1);
            *(uint2*)&Bh[q][kr * B_STR + nq] = make_uint2(h0, h1);
            *(uint2*)&Bl[q][kr * B_STR + nq] = make_uint2(l0, l1);
        }
        __syncthreads();
    }

    // epilogue: atomic accumulate (out pre-zeroed by memset)
    #pragma unroll
    for (int mt = 0; mt < 2; mt++) {
        #pragma unroll
        for (int half = 0; half < 2; half++) {
            int r = m0 + warpM * 32 + mt * 16 + half * 8 + gq;
            if (r >= cnt) continue;
            int tok; float w;
            if (shared_e) { tok = r; w = 1.0f; }
            else {
                int grow = off + r;
                tok = g_rowlist[grow];
                w   = g_roww[grow] * 2.5f;
            }
            float* op = out + (size_t)tok * ND + n0 + warpN * 32;
            #pragma unroll
            for (int nt = 0; nt < 4; nt++) {
                atomicAdd(&op[nt * 8 + 2 * tq],     w * acc[mt][nt][half * 2 + 0]);
                atomicAdd(&op[nt * 8 + 2 * tq + 1], w * acc[mt][nt][half * 2 + 1]);
            }
        }
    }
}

// ---------------- launch ----------------
extern "C" void kernel_launch(void* const* d_in, const int* in_sizes, int n_in,
                              void* d_out, int out_size) {
    const float* x       = (const float*)d_in[0];
    const float* gate_w  = (const float*)d_in[1];
    const float* gate_b  = (const float*)d_in[2];
    const float* w_gate  = (const float*)d_in[3];
    const float* w_up    = (const float*)d_in[4];
    const float* w_down  = (const float*)d_in[5];
    const float* sw_gate = (const float*)d_in[6];
    const float* sw_up   = (const float*)d_in[7];
    const float* sw_down = (const float*)d_in[8];
    float* out = (float*)d_out;

    gate_kernel <<<NT, 256>>>(x, gate_w, gate_b);
    route_kernel<<<1, 1024>>>();

    // gated: z=0,1 shared n-slices; z=2..33 routed experts. No dead n-blocks.
    gemm_gated_all<<<dim3(NT / 128, 22, NE + 2), 256>>>(
        x, w_gate, w_up, sw_gate, sw_up);

    // down: out zero-init, then all paths atomically accumulate.
    cudaMemsetAsync(out, 0, (size_t)out_size * sizeof(float));
    gemm_down_all<<<dim3(NT / 128, ND / 64, NE + 2), 256>>>(
        w_down, sw_down, out);
}

// round 15
// speedup vs baseline: 1.1930x; 1.1069x over previous
#include <cuda_runtime.h>
#include <cuda_fp16.h>
#include <math.h>
#include <stdint.h>

// Problem constants
#define NT   1024          // tokens
#define ND   2048          // hidden dim
#define NE   32            // experts
#define NI   1408          // routed intermediate
#define NSI  2816          // shared intermediate
#define NG   8             // groups
#define EPG  4             // experts per group
#define NA   (NT * 4)      // total assignments (top_k = 4)

// ---------------- device scratch ----------------
__device__ float g_h [NA * NI];    // routed  silu(x@Wg)*(x@Wu)  (fp32)
__device__ float g_hs[NT * NSI];   // shared  silu(x@Sg)*(x@Su)
__device__ int   g_rowlist[NA];
__device__ float g_roww  [NA];
__device__ int   g_counts [NE];
__device__ int   g_offsets[NE];
__device__ int   g_tid4[NA];
__device__ float g_tw4 [NA];

// ---------------- fp16 split + mma helpers ----------------
// A-side: v = h + l, both fp16 (exact to ~2^-22). Packs (v0,v1) -> u32.
__device__ __forceinline__ void split2(float v0, float v1, unsigned& h, unsigned& l) {
    __half2 hh = __floats2half2_rn(v0, v1);
    float2 hf = __half22float2(hh);
    __half2 ll = __floats2half2_rn(v0 - hf.x, v1 - hf.y);
    h = *(unsigned*)&hh;
    l = *(unsigned*)&ll;
}
// B-side: single fp16 rounding.
__device__ __forceinline__ unsigned pack2h(float v0, float v1) {
    __half2 hh = __floats2half2_rn(v0, v1);
    return *(unsigned*)&hh;
}

__device__ __forceinline__ void mma_f16(float* d, const unsigned* a, const unsigned* b) {
    asm volatile(
        "mma.sync.aligned.m16n8k16.row.col.f32.f16.f16.f32 "
        "{%0,%1,%2,%3}, {%4,%5,%6,%7}, {%8,%9}, {%0,%1,%2,%3};"
        : "+f"(d[0]), "+f"(d[1]), "+f"(d[2]), "+f"(d[3])
        : "r"(a[0]), "r"(a[1]), "r"(a[2]), "r"(a[3]), "r"(b[0]), "r"(b[1]));
}

__device__ __forceinline__ void ldsm4(unsigned* r, uint32_t a) {
    asm volatile("ldmatrix.sync.aligned.m8n8.x4.shared.b16 {%0,%1,%2,%3}, [%4];"
        : "=r"(r[0]), "=r"(r[1]), "=r"(r[2]), "=r"(r[3]) : "r"(a));
}
__device__ __forceinline__ void ldsm4t(unsigned* r, uint32_t a) {
    asm volatile("ldmatrix.sync.aligned.m8n8.x4.trans.shared.b16 {%0,%1,%2,%3}, [%4];"
        : "=r"(r[0]), "=r"(r[1]), "=r"(r[2]), "=r"(r[3]) : "r"(a));
}
__device__ __forceinline__ uint32_t sptr(const void* p) {
    return (uint32_t)__cvta_generic_to_shared(p);
}

// ---------------- routing kernels ----------------
__global__ void gate_kernel(const float* __restrict__ x,
                            const float* __restrict__ gw,
                            const float* __restrict__ gb) {
    __shared__ float xs[ND];
    __shared__ float logit[NE];
    int t = blockIdx.x;
    for (int k = threadIdx.x; k < ND; k += 256) xs[k] = x[(size_t)t * ND + k];
    __syncthreads();
    int e = threadIdx.x >> 3;
    int j = threadIdx.x & 7;
    const float* w = gw + (size_t)e * ND;
    float s = 0.f;
    for (int k = j; k < ND; k += 8) s += xs[k] * w[k];
    s += __shfl_xor_sync(0xffffffffu, s, 1);
    s += __shfl_xor_sync(0xffffffffu, s, 2);
    s += __shfl_xor_sync(0xffffffffu, s, 4);
    if (j == 0) logit[e] = s + gb[e];
    __syncthreads();
    if (threadIdx.x == 0) {
        float sc[NE], scb[NE];
        #pragma unroll
        for (int i = 0; i < NE; i++) {
            float v = 1.f / (1.f + expf(-logit[i]));
            sc[i]  = v;
            scb[i] = v + gb[i];
        }
        float gs[NG];
        #pragma unroll
        for (int g = 0; g < NG; g++) {
            float m1 = -1e30f, m2 = -1e30f;
            #pragma unroll
            for (int q = 0; q < EPG; q++) {
                float v = scb[g * EPG + q];
                if (v > m1) { m2 = m1; m1 = v; } else if (v > m2) { m2 = v; }
            }
            gs[g] = m1 + m2;
        }
        bool gsel[NG];
        #pragma unroll
        for (int g = 0; g < NG; g++) gsel[g] = false;
        for (int r = 0; r < 4; r++) {
            float best = -1e30f; int bi = 0;
            for (int g = 0; g < NG; g++)
                if (!gsel[g] && gs[g] > best) { best = gs[g]; bi = g; }
            gsel[bi] = true;
        }
        float tmp[NE];
        #pragma unroll
        for (int i = 0; i < NE; i++) tmp[i] = gsel[i / EPG] ? scb[i] : 0.0f;
        int ids[4]; float tw[4]; float wsum = 0.f;
        for (int r = 0; r < 4; r++) {
            float best = -1e30f; int bi = 0;
            for (int i = 0; i < NE; i++)
                if (tmp[i] > best) { best = tmp[i]; bi = i; }
            tmp[bi] = -1e30f;
            ids[r] = bi;
            tw[r] = sc[bi];
            wsum += tw[r];
        }
        float inv = 1.f / wsum;
        for (int r = 0; r < 4; r++) {
            g_tid4[t * 4 + r] = ids[r];
            g_tw4 [t * 4 + r] = tw[r] * inv;
        }
    }
}

// fused count + scan + scatter, single block of 1024 threads
__global__ void route_kernel() {
    __shared__ int cnts[NE];
    __shared__ int curs[NE];
    int tid = threadIdx.x;
    if (tid < NE) cnts[tid] = 0;
    __syncthreads();
    for (int i = tid; i < NA; i += 1024)
        atomicAdd(&cnts[g_tid4[i]], 1);
    __syncthreads();
    if (tid < 32) {
        int c = cnts[tid];
        int v = c;
        #pragma unroll
        for (int o = 1; o < 32; o <<= 1) {
            int u = __shfl_up_sync(0xffffffffu, v, o);
            if (tid >= o) v += u;
        }
        g_counts[tid]  = c;
        g_offsets[tid] = v - c;
        curs[tid]      = v - c;
    }
    __syncthreads();
    for (int i = tid; i < NA; i += 1024) {
        int e = g_tid4[i];
        int pos = atomicAdd(&curs[e], 1);
        g_rowlist[pos] = i >> 2;
        g_roww[pos]    = g_tw4[i];
    }
}

// ============================================================================
// fp16 2-term mma.sync GEMMs (A = Ah+Al fp16 exact; B single fp16):
//   D = Ah*B + Al*B   -- 2 mma per tile (was 3), one B operand tile (was 2).
// LDSM fragments, 2-stage ping-pong, R14 scheduling:
// Gated grid (8, 22, 34): z=0,1 shared n-slices (NSI); z>=2 routed (NI).
// Down grid (8, 32, 34): z=0,1 shared K-halves; z>=2 routed. Uniform 88 chunks.
// Block BM=128, BN=64, BK=16; 256 thr = 8 warps (4M x 2N); warp tile 32x32.
// ============================================================================

#define A_STR 24
#define B_STR 72
#define A_SZ  (128 * A_STR)
#define B_SZ  (16 * B_STR)
#define A_SZB (A_SZ * 2)
#define B_SZB (B_SZ * 2)

// ---------------- GEMM 1: H = silu(A@Wg) * (A@Wu) ----------------
__global__ void __launch_bounds__(256, 2)
gemm_gated_all(const float* __restrict__ x,
               const float* __restrict__ Wg,  const float* __restrict__ Wu,
               const float* __restrict__ SWg, const float* __restrict__ SWu) {
    int z = blockIdx.z;
    bool shared_e = (z < 2);
    int cnt, off, idim, n0;
    const float* wg;
    const float* wu;
    float* H;
    if (shared_e) {
        cnt = NT; off = 0; idim = NSI;
        wg = SWg; wu = SWu; H = g_hs;
        n0 = (z * 22 + blockIdx.y) * 64;
    } else {
        int e = z - 2;
        cnt = g_counts[e]; off = g_offsets[e]; idim = NI;
        wg = Wg + (size_t)e * ND * NI;
        wu = Wu + (size_t)e * ND * NI;
        H = g_h;
        n0 = blockIdx.y * 64;
    }
    int m0 = blockIdx.x * 128;
    if (m0 >= cnt) return;

    __shared__ __align__(16) unsigned short Ah[2][A_SZ], Al[2][A_SZ];
    __shared__ __align__(16) unsigned short Bg[2][B_SZ], Bu[2][B_SZ];

    int tid  = threadIdx.x;
    int lane = tid & 31, wid = tid >> 5;
    int warpM = wid >> 1, warpN = wid & 1;
    int gq = lane >> 2, tq = lane & 3;

    // ---- A staging: 2 float4 per thread over 128x16 fp32 ----
    const float* aptr[2]; int mA[2], kA[2];
    #pragma unroll
    for (int l = 0; l < 2; l++) {
        int idx = tid + l * 256;
        mA[l] = idx >> 2; kA[l] = (idx & 3) << 2;
        int m = m0 + mA[l];
        int tok;
        if (shared_e) tok = (m < cnt) ? m : 0;
        else          tok = (m < cnt) ? g_rowlist[off + m] : 0;
        aptr[l] = x + (size_t)tok * ND + kA[l];
    }
    // ---- B staging: 2 matrices x 128 threads; rows kr, kr+8; 4 n-vals ----
    int mat = tid >> 7, rr = tid & 127;
    int kr  = rr >> 4, nq = (rr & 15) << 2;
    const float* bp = (mat ? wu : wg) + (size_t)kr * idim + n0 + nq;
    unsigned short* B0 = mat ? Bu[0] : Bg[0];

    // ---- LDSM base addresses ----
    int arow = lane & 15, acolb = (lane >> 4) << 4;
    uint32_t a_ld_h[2], a_ld_l[2];
    #pragma unroll
    for (int mt = 0; mt < 2; mt++) {
        int r = warpM * 32 + mt * 16 + arow;
        a_ld_h[mt] = sptr(Ah) + r * (A_STR * 2) + acolb;
        a_ld_l[mt] = sptr(Al) + r * (A_STR * 2) + acolb;
    }
    int bkr = lane & 15;
    int bcolb = (warpN * 32) * 2 + ((lane >> 4) << 4);
    uint32_t b_ld[2][2];
    const void* barr[2] = {Bg, Bu};
    #pragma unroll
    for (int a = 0; a < 2; a++)
        #pragma unroll
        for (int np = 0; np < 2; np++)
            b_ld[a][np] = sptr(barr[a]) + bkr * (B_STR * 2) + bcolb + np * 32;

    float accg[2][4][4], accu[2][4][4];
    #pragma unroll
    for (int mt = 0; mt < 2; mt++)
        #pragma unroll
        for (int nt = 0; nt < 4; nt++)
            #pragma unroll
            for (int r = 0; r < 4; r++) { accg[mt][nt][r] = 0.f; accu[mt][nt][r] = 0.f; }

    // ---- prologue: chunk 0 -> stage 0 ----
    float4 ra0 = *(const float4*)(aptr[0]);
    float4 ra1 = *(const float4*)(aptr[1]);
    float4 rb0 = *(const float4*)(bp);
    float4 rb1 = *(const float4*)(bp + (size_t)8 * idim);
    {
        unsigned h0, l0, h1, l1;
        split2(ra0.x, ra0.y, h0, l0); split2(ra0.z, ra0.w, h1, l1);
        *(uint2*)&Ah[0][mA[0] * A_STR + kA[0]] = make_uint2(h0, h1);
        *(uint2*)&Al[0][mA[0] * A_STR + kA[0]] = make_uint2(l0, l1);
        split2(ra1.x, ra1.y, h0, l0); split2(ra1.z, ra1.w, h1, l1);
        *(uint2*)&Ah[0][mA[1] * A_STR + kA[1]] = make_uint2(h0, h1);
        *(uint2*)&Al[0][mA[1] * A_STR + kA[1]] = make_uint2(l0, l1);
        *(uint2*)&B0[kr * B_STR + nq] =
            make_uint2(pack2h(rb0.x, rb0.y), pack2h(rb0.z, rb0.w));
        *(uint2*)&B0[(kr + 8) * B_STR + nq] =
            make_uint2(pack2h(rb1.x, rb1.y), pack2h(rb1.z, rb1.w));
    }
    __syncthreads();

    const int NCH = ND / 16;
    for (int c = 0; c < NCH; c++) {
        int p = c & 1;
        bool more = (c + 1 < NCH);
        if (more) {
            int kt = (c + 1) * 16;
            ra0 = *(const float4*)(aptr[0] + kt);
            ra1 = *(const float4*)(aptr[1] + kt);
            rb0 = *(const float4*)(bp + (size_t)kt * idim);
            rb1 = *(const float4*)(bp + (size_t)(kt + 8) * idim);
        }
        {
            uint32_t ao = p * A_SZB, bo = p * B_SZB;
            unsigned ah[2][4], al[2][4];
            ldsm4(ah[0], a_ld_h[0] + ao); ldsm4(ah[1], a_ld_h[1] + ao);
            ldsm4(al[0], a_ld_l[0] + ao); ldsm4(al[1], a_ld_l[1] + ao);
            #pragma unroll
            for (int np = 0; np < 2; np++) {
                unsigned bg[4], bu[4];
                ldsm4t(bg, b_ld[0][np] + bo);
                ldsm4t(bu, b_ld[1][np] + bo);
                #pragma unroll
                for (int j = 0; j < 2; j++) {
                    int nt = np * 2 + j;
                    #pragma unroll
                    for (int mt = 0; mt < 2; mt++) {
                        mma_f16(accg[mt][nt], ah[mt], &bg[2 * j]);
                        mma_f16(accg[mt][nt], al[mt], &bg[2 * j]);
                        mma_f16(accu[mt][nt], ah[mt], &bu[2 * j]);
                        mma_f16(accu[mt][nt], al[mt], &bu[2 * j]);
                    }
                }
            }
        }
        if (more) {
            int q = p ^ 1;
            unsigned short* Bq = mat ? Bu[q] : Bg[q];
            unsigned h0, l0, h1, l1;
            split2(ra0.x, ra0.y, h0, l0); split2(ra0.z, ra0.w, h1, l1);
            *(uint2*)&Ah[q][mA[0] * A_STR + kA[0]] = make_uint2(h0, h1);
            *(uint2*)&Al[q][mA[0] * A_STR + kA[0]] = make_uint2(l0, l1);
            split2(ra1.x, ra1.y, h0, l0); split2(ra1.z, ra1.w, h1, l1);
            *(uint2*)&Ah[q][mA[1] * A_STR + kA[1]] = make_uint2(h0, h1);
            *(uint2*)&Al[q][mA[1] * A_STR + kA[1]] = make_uint2(l0, l1);
            *(uint2*)&Bq[kr * B_STR + nq] =
                make_uint2(pack2h(rb0.x, rb0.y), pack2h(rb0.z, rb0.w));
            *(uint2*)&Bq[(kr + 8) * B_STR + nq] =
                make_uint2(pack2h(rb1.x, rb1.y), pack2h(rb1.z, rb1.w));
        }
        __syncthreads();
    }

    // epilogue: silu(gate) * up -> fp32 H
    #pragma unroll
    for (int mt = 0; mt < 2; mt++) {
        #pragma unroll
        for (int half = 0; half < 2; half++) {
            int r = m0 + warpM * 32 + mt * 16 + half * 8 + gq;
            if (r >= cnt) continue;
            float* hrow = H + (size_t)(off + r) * idim + n0 + warpN * 32;
            #pragma unroll
            for (int nt = 0; nt < 4; nt++) {
                float gv0 = accg[mt][nt][half * 2 + 0];
                float gv1 = accg[mt][nt][half * 2 + 1];
                float uv0 = accu[mt][nt][half * 2 + 0];
                float uv1 = accu[mt][nt][half * 2 + 1];
                float2 hv;
                hv.x = gv0 / (1.f + expf(-gv0)) * uv0;
                hv.y = gv1 / (1.f + expf(-gv1)) * uv1;
                *(float2*)&hrow[nt * 8 + 2 * tq] = hv;
            }
        }
    }
}

// ---------------- GEMM 2: out += w * H @ Wd  (out pre-zeroed; all atomic) ----
__global__ void __launch_bounds__(256, 2)
gemm_down_all(const float* __restrict__ Wd, const float* __restrict__ SWd,
              float* __restrict__ out) {
    int z = blockIdx.z;
    bool shared_e = (z < 2);
    int cnt, off, astride, kbase;
    const float* wd;
    const float* Hsrc;
    if (shared_e) {
        cnt = NT; off = 0; astride = NSI; kbase = z * NI;  // K-half of NSI
        wd = SWd + (size_t)kbase * ND;
        Hsrc = g_hs;
    } else {
        int e = z - 2;
        cnt = g_counts[e]; off = g_offsets[e]; astride = NI; kbase = 0;
        wd = Wd + (size_t)e * NI * ND;
        Hsrc = g_h;
    }
    int m0 = blockIdx.x * 128;
    if (m0 >= cnt) return;
    int n0 = blockIdx.y * 64;

    __shared__ __align__(16) unsigned short Ah[2][A_SZ], Al[2][A_SZ];
    __shared__ __align__(16) unsigned short Bh[2][B_SZ];

    int tid  = threadIdx.x;
    int lane = tid & 31, wid = tid >> 5;
    int warpM = wid >> 1, warpN = wid & 1;
    int gq = lane >> 2, tq = lane & 3;

    const float* aptr[2]; int mA[2], kA[2];
    #pragma unroll
    for (int l = 0; l < 2; l++) {
        int idx = tid + l * 256;
        mA[l] = idx >> 2; kA[l] = (idx & 3) << 2;
        int m = m0 + mA[l];
        int hr = (m < cnt) ? (off + m) : off;
        aptr[l] = Hsrc + (size_t)hr * astride + kbase + kA[l];
    }
    int kr = tid >> 4, nq = (tid & 15) << 2;
    const float* bp = wd + (size_t)kr * ND + n0 + nq;

    int arow = lane & 15, acolb = (lane >> 4) << 4;
    uint32_t a_ld_h[2], a_ld_l[2];
    #pragma unroll
    for (int mt = 0; mt < 2; mt++) {
        int r = warpM * 32 + mt * 16 + arow;
        a_ld_h[mt] = sptr(Ah) + r * (A_STR * 2) + acolb;
        a_ld_l[mt] = sptr(Al) + r * (A_STR * 2) + acolb;
    }
    int bkr = lane & 15;
    int bcolb = (warpN * 32) * 2 + ((lane >> 4) << 4);
    uint32_t b_ld[2];
    #pragma unroll
    for (int np = 0; np < 2; np++)
        b_ld[np] = sptr(Bh) + bkr * (B_STR * 2) + bcolb + np * 32;

    float acc[2][4][4];
    #pragma unroll
    for (int mt = 0; mt < 2; mt++)
        #pragma unroll
        for (int nt = 0; nt < 4; nt++)
            #pragma unroll
            for (int r = 0; r < 4; r++) acc[mt][nt][r] = 0.f;

    float4 ra0 = *(const float4*)(aptr[0]);
    float4 ra1 = *(const float4*)(aptr[1]);
    float4 rb  = *(const float4*)(bp);
    {
        unsigned h0, l0, h1, l1;
        split2(ra0.x, ra0.y, h0, l0); split2(ra0.z, ra0.w, h1, l1);
        *(uint2*)&Ah[0][mA[0] * A_STR + kA[0]] = make_uint2(h0, h1);
        *(uint2*)&Al[0][mA[0] * A_STR + kA[0]] = make_uint2(l0, l1);
        split2(ra1.x, ra1.y, h0, l0); split2(ra1.z, ra1.w, h1, l1);
        *(uint2*)&Ah[0][mA[1] * A_STR + kA[1]] = make_uint2(h0, h1);
        *(uint2*)&Al[0][mA[1] * A_STR + kA[1]] = make_uint2(l0, l1);
        *(uint2*)&Bh[0][kr * B_STR + nq] =
            make_uint2(pack2h(rb.x, rb.y), pack2h(rb.z, rb.w));
    }
    __syncthreads();

    const int NCH = NI / 16;   // 88 chunks for ALL blocks (uniform duration)
    for (int c = 0; c < NCH; c++) {
        int p = c & 1;
        bool more = (c + 1 < NCH);
        if (more) {
            int kt = (c + 1) * 16;
            ra0 = *(const float4*)(aptr[0] + kt);
            ra1 = *(const float4*)(aptr[1] + kt);
            rb  = *(const float4*)(bp + (size_t)kt * ND);
        }
        {
            uint32_t ao = p * A_SZB, bo = p * B_SZB;
            unsigned ah[2][4], al[2][4];
            ldsm4(ah[0], a_ld_h[0] + ao); ldsm4(ah[1], a_ld_h[1] + ao);
            ldsm4(al[0], a_ld_l[0] + ao); ldsm4(al[1], a_ld_l[1] + ao);
            #pragma unroll
            for (int np = 0; np < 2; np++) {
                unsigned bh[4];
                ldsm4t(bh, b_ld[np] + bo);
                #pragma unroll
                for (int j = 0; j < 2; j++) {
                    int nt = np * 2 + j;
                    #pragma unroll
                    for (int mt = 0; mt < 2; mt++) {
                        mma_f16(acc[mt][nt], ah[mt], &bh[2 * j]);
                        mma_f16(acc[mt][nt], al[mt], &bh[2 * j]);
                    }
                }
            }
        }
        if (more) {
            int q = p ^ 1;
            unsigned h0, l0, h1, l1;
            split2(ra0.x, ra0.y, h0, l0); split2(ra0.z, ra0.w, h1, l1);
            *(uint2*)&Ah[q][mA[0] * A_STR + kA[0]] = make_uint2(h0, h1);
            *(uint2*)&Al[q][mA[0] * A_STR + kA[0]] = make_uint2(l0, l1);
            split2(ra1.x, ra1.y, h0, l0); split2(ra1.z, ra1.w, h1, l1);
            *(uint2*)&Ah[q][mA[1] * A_STR + kA[1]] = make_uint2(h0, h1);
            *(uint2*)&Al[q][mA[1] * A_STR + kA[1]] = make_uint2(l0, l1);
            *(uint2*)&Bh[q][kr * B_STR + nq] =
                make_uint2(pack2h(rb.x, rb.y), pack2h(rb.z, rb.w));
        }
        __syncthreads();
    }

    // epilogue: atomic accumulate (out pre-zeroed by memset)
    #pragma unroll
    for (int mt = 0; mt < 2; mt++) {
        #pragma unroll
        for (int half = 0; half < 2; half++) {
            int r = m0 + warpM * 32 + mt * 16 + half * 8 + gq;
            if (r >= cnt) continue;
            int tok; float w;
            if (shared_e) { tok = r; w = 1.0f; }
            else {
                int grow = off + r;
                tok = g_rowlist[grow];
                w   = g_roww[grow] * 2.5f;
            }
            float* op = out + (size_t)tok * ND + n0 + warpN * 32;
            #pragma unroll
            for (int nt = 0; nt < 4; nt++) {
                atomicAdd(&op[nt * 8 + 2 * tq],     w * acc[mt][nt][half * 2 + 0]);
                atomicAdd(&op[nt * 8 + 2 * tq + 1], w * acc[mt][nt][half * 2 + 1]);
            }
        }
    }
}

// ---------------- launch ----------------
extern "C" void kernel_launch(void* const* d_in, const int* in_sizes, int n_in,
                              void* d_out, int out_size) {
    const float* x       = (const float*)d_in[0];
    const float* gate_w  = (const float*)d_in[1];
    const float* gate_b  = (const float*)d_in[2];
    const float* w_gate  = (const float*)d_in[3];
    const float* w_up    = (const float*)d_in[4];
    const float* w_down  = (const float*)d_in[5];
    const float* sw_gate = (const float*)d_in[6];
    const float* sw_up   = (const float*)d_in[7];
    const float* sw_down = (const float*)d_in[8];
    float* out = (float*)d_out;

    gate_kernel <<<NT, 256>>>(x, gate_w, gate_b);
    route_kernel<<<1, 1024>>>();

    // gated: z=0,1 shared n-slices; z=2..33 routed experts. No dead n-blocks.
    gemm_gated_all<<<dim3(NT / 128, 22, NE + 2), 256>>>(
        x, w_gate, w_up, sw_gate, sw_up);

    // down: out zero-init, then all paths atomically accumulate.
    cudaMemsetAsync(out, 0, (size_t)out_size * sizeof(float));
    gemm_down_all<<<dim3(NT / 128, ND / 64, NE + 2), 256>>>(
        w_down, sw_down, out);
}

// round 16
// speedup vs baseline: 1.2339x; 1.0342x over previous
#include <cuda_runtime.h>
#include <cuda_fp16.h>
#include <math.h>
#include <stdint.h>

// Problem constants
#define NT   1024          // tokens
#define ND   2048          // hidden dim
#define NE   32            // experts
#define NI   1408          // routed intermediate
#define NSI  2816          // shared intermediate
#define NG   8             // groups
#define EPG  4             // experts per group
#define NA   (NT * 4)      // total assignments (top_k = 4)

// ---------------- device scratch ----------------
__device__ float g_h [NA * NI];    // routed  silu(x@Wg)*(x@Wu)  (fp32)
__device__ float g_hs[NT * NSI];   // shared  silu(x@Sg)*(x@Su)
__device__ int   g_rowlist[NA];
__device__ float g_roww  [NA];
__device__ int   g_counts [NE];
__device__ int   g_offsets[NE];
__device__ int   g_tid4[NA];
__device__ float g_tw4 [NA];

// ---------------- fp16 helpers ----------------
__device__ __forceinline__ unsigned pack2h(float v0, float v1) {
    __half2 hh = __floats2half2_rn(v0, v1);
    return *(unsigned*)&hh;
}

__device__ __forceinline__ void mma_f16(float* d, const unsigned* a, const unsigned* b) {
    asm volatile(
        "mma.sync.aligned.m16n8k16.row.col.f32.f16.f16.f32 "
        "{%0,%1,%2,%3}, {%4,%5,%6,%7}, {%8,%9}, {%0,%1,%2,%3};"
        : "+f"(d[0]), "+f"(d[1]), "+f"(d[2]), "+f"(d[3])
        : "r"(a[0]), "r"(a[1]), "r"(a[2]), "r"(a[3]), "r"(b[0]), "r"(b[1]));
}

__device__ __forceinline__ void ldsm4(unsigned* r, uint32_t a) {
    asm volatile("ldmatrix.sync.aligned.m8n8.x4.shared.b16 {%0,%1,%2,%3}, [%4];"
        : "=r"(r[0]), "=r"(r[1]), "=r"(r[2]), "=r"(r[3]) : "r"(a));
}
__device__ __forceinline__ void ldsm4t(unsigned* r, uint32_t a) {
    asm volatile("ldmatrix.sync.aligned.m8n8.x4.trans.shared.b16 {%0,%1,%2,%3}, [%4];"
        : "=r"(r[0]), "=r"(r[1]), "=r"(r[2]), "=r"(r[3]) : "r"(a));
}
__device__ __forceinline__ uint32_t sptr(const void* p) {
    return (uint32_t)__cvta_generic_to_shared(p);
}

// ---------------- routing kernels ----------------
__global__ void gate_kernel(const float* __restrict__ x,
                            const float* __restrict__ gw,
                            const float* __restrict__ gb) {
    __shared__ float xs[ND];
    __shared__ float logit[NE];
    int t = blockIdx.x;
    for (int k = threadIdx.x; k < ND; k += 256) xs[k] = x[(size_t)t * ND + k];
    __syncthreads();
    int e = threadIdx.x >> 3;
    int j = threadIdx.x & 7;
    const float* w = gw + (size_t)e * ND;
    float s = 0.f;
    for (int k = j; k < ND; k += 8) s += xs[k] * w[k];
    s += __shfl_xor_sync(0xffffffffu, s, 1);
    s += __shfl_xor_sync(0xffffffffu, s, 2);
    s += __shfl_xor_sync(0xffffffffu, s, 4);
    if (j == 0) logit[e] = s + gb[e];
    __syncthreads();
    if (threadIdx.x == 0) {
        float sc[NE], scb[NE];
        #pragma unroll
        for (int i = 0; i < NE; i++) {
            float v = 1.f / (1.f + expf(-logit[i]));
            sc[i]  = v;
            scb[i] = v + gb[i];
        }
        float gs[NG];
        #pragma unroll
        for (int g = 0; g < NG; g++) {
            float m1 = -1e30f, m2 = -1e30f;
            #pragma unroll
            for (int q = 0; q < EPG; q++) {
                float v = scb[g * EPG + q];
                if (v > m1) { m2 = m1; m1 = v; } else if (v > m2) { m2 = v; }
            }
            gs[g] = m1 + m2;
        }
        bool gsel[NG];
        #pragma unroll
        for (int g = 0; g < NG; g++) gsel[g] = false;
        for (int r = 0; r < 4; r++) {
            float best = -1e30f; int bi = 0;
            for (int g = 0; g < NG; g++)
                if (!gsel[g] && gs[g] > best) { best = gs[g]; bi = g; }
            gsel[bi] = true;
        }
        float tmp[NE];
        #pragma unroll
        for (int i = 0; i < NE; i++) tmp[i] = gsel[i / EPG] ? scb[i] : 0.0f;
        int ids[4]; float tw[4]; float wsum = 0.f;
        for (int r = 0; r < 4; r++) {
            float best = -1e30f; int bi = 0;
            for (int i = 0; i < NE; i++)
                if (tmp[i] > best) { best = tmp[i]; bi = i; }
            tmp[bi] = -1e30f;
            ids[r] = bi;
            tw[r] = sc[bi];
            wsum += tw[r];
        }
        float inv = 1.f / wsum;
        for (int r = 0; r < 4; r++) {
            g_tid4[t * 4 + r] = ids[r];
            g_tw4 [t * 4 + r] = tw[r] * inv;
        }
    }
}

// fused count + scan + scatter, single block of 1024 threads
__global__ void route_kernel() {
    __shared__ int cnts[NE];
    __shared__ int curs[NE];
    int tid = threadIdx.x;
    if (tid < NE) cnts[tid] = 0;
    __syncthreads();
    for (int i = tid; i < NA; i += 1024)
        atomicAdd(&cnts[g_tid4[i]], 1);
    __syncthreads();
    if (tid < 32) {
        int c = cnts[tid];
        int v = c;
        #pragma unroll
        for (int o = 1; o < 32; o <<= 1) {
            int u = __shfl_up_sync(0xffffffffu, v, o);
            if (tid >= o) v += u;
        }
        g_counts[tid]  = c;
        g_offsets[tid] = v - c;
        curs[tid]      = v - c;
    }
    __syncthreads();
    for (int i = tid; i < NA; i += 1024) {
        int e = g_tid4[i];
        int pos = atomicAdd(&curs[e], 1);
        g_rowlist[pos] = i >> 2;
        g_roww[pos]    = g_tw4[i];
    }
}

// ============================================================================
// Pure fp16 mma.sync GEMMs (A and B single fp16, fp32 accum):
//   gated: 2 mma per (mt,nt) [gate & up];  down: 1 mma per (mt,nt).
// LDSM fragments, 2-stage ping-pong, R14 scheduling:
// Gated grid (8, 22, 34): z=0,1 shared n-slices (NSI); z>=2 routed (NI).
// Down grid (8, 32, 34): z=0,1 shared K-halves; z>=2 routed. Uniform 88 chunks.
// Block BM=128, BN=64, BK=16; 256 thr = 8 warps (4M x 2N); warp tile 32x32.
// ============================================================================

#define A_STR 24
#define B_STR 72
#define A_SZ  (128 * A_STR)
#define B_SZ  (16 * B_STR)
#define A_SZB (A_SZ * 2)
#define B_SZB (B_SZ * 2)

// ---------------- GEMM 1: H = silu(A@Wg) * (A@Wu) ----------------
__global__ void __launch_bounds__(256, 2)
gemm_gated_all(const float* __restrict__ x,
               const float* __restrict__ Wg,  const float* __restrict__ Wu,
               const float* __restrict__ SWg, const float* __restrict__ SWu) {
    int z = blockIdx.z;
    bool shared_e = (z < 2);
    int cnt, off, idim, n0;
    const float* wg;
    const float* wu;
    float* H;
    if (shared_e) {
        cnt = NT; off = 0; idim = NSI;
        wg = SWg; wu = SWu; H = g_hs;
        n0 = (z * 22 + blockIdx.y) * 64;
    } else {
        int e = z - 2;
        cnt = g_counts[e]; off = g_offsets[e]; idim = NI;
        wg = Wg + (size_t)e * ND * NI;
        wu = Wu + (size_t)e * ND * NI;
        H = g_h;
        n0 = blockIdx.y * 64;
    }
    int m0 = blockIdx.x * 128;
    if (m0 >= cnt) return;

    __shared__ __align__(16) unsigned short Ah[2][A_SZ];
    __shared__ __align__(16) unsigned short Bg[2][B_SZ], Bu[2][B_SZ];

    int tid  = threadIdx.x;
    int lane = tid & 31, wid = tid >> 5;
    int warpM = wid >> 1, warpN = wid & 1;
    int gq = lane >> 2, tq = lane & 3;

    // ---- A staging: 2 float4 per thread over 128x16 fp32 ----
    const float* aptr[2]; int mA[2], kA[2];
    #pragma unroll
    for (int l = 0; l < 2; l++) {
        int idx = tid + l * 256;
        mA[l] = idx >> 2; kA[l] = (idx & 3) << 2;
        int m = m0 + mA[l];
        int tok;
        if (shared_e) tok = (m < cnt) ? m : 0;
        else          tok = (m < cnt) ? g_rowlist[off + m] : 0;
        aptr[l] = x + (size_t)tok * ND + kA[l];
    }
    // ---- B staging: 2 matrices x 128 threads; rows kr, kr+8; 4 n-vals ----
    int mat = tid >> 7, rr = tid & 127;
    int kr  = rr >> 4, nq = (rr & 15) << 2;
    const float* bp = (mat ? wu : wg) + (size_t)kr * idim + n0 + nq;
    unsigned short* B0 = mat ? Bu[0] : Bg[0];

    // ---- LDSM base addresses ----
    int arow = lane & 15, acolb = (lane >> 4) << 4;
    uint32_t a_ld[2];
    #pragma unroll
    for (int mt = 0; mt < 2; mt++) {
        int r = warpM * 32 + mt * 16 + arow;
        a_ld[mt] = sptr(Ah) + r * (A_STR * 2) + acolb;
    }
    int bkr = lane & 15;
    int bcolb = (warpN * 32) * 2 + ((lane >> 4) << 4);
    uint32_t b_ld[2][2];
    const void* barr[2] = {Bg, Bu};
    #pragma unroll
    for (int a = 0; a < 2; a++)
        #pragma unroll
        for (int np = 0; np < 2; np++)
            b_ld[a][np] = sptr(barr[a]) + bkr * (B_STR * 2) + bcolb + np * 32;

    float accg[2][4][4], accu[2][4][4];
    #pragma unroll
    for (int mt = 0; mt < 2; mt++)
        #pragma unroll
        for (int nt = 0; nt < 4; nt++)
            #pragma unroll
            for (int r = 0; r < 4; r++) { accg[mt][nt][r] = 0.f; accu[mt][nt][r] = 0.f; }

    // ---- prologue: chunk 0 -> stage 0 ----
    float4 ra0 = *(const float4*)(aptr[0]);
    float4 ra1 = *(const float4*)(aptr[1]);
    float4 rb0 = *(const float4*)(bp);
    float4 rb1 = *(const float4*)(bp + (size_t)8 * idim);
    {
        *(uint2*)&Ah[0][mA[0] * A_STR + kA[0]] =
            make_uint2(pack2h(ra0.x, ra0.y), pack2h(ra0.z, ra0.w));
        *(uint2*)&Ah[0][mA[1] * A_STR + kA[1]] =
            make_uint2(pack2h(ra1.x, ra1.y), pack2h(ra1.z, ra1.w));
        *(uint2*)&B0[kr * B_STR + nq] =
            make_uint2(pack2h(rb0.x, rb0.y), pack2h(rb0.z, rb0.w));
        *(uint2*)&B0[(kr + 8) * B_STR + nq] =
            make_uint2(pack2h(rb1.x, rb1.y), pack2h(rb1.z, rb1.w));
    }
    __syncthreads();

    const int NCH = ND / 16;
    for (int c = 0; c < NCH; c++) {
        int p = c & 1;
        bool more = (c + 1 < NCH);
        if (more) {
            int kt = (c + 1) * 16;
            ra0 = *(const float4*)(aptr[0] + kt);
            ra1 = *(const float4*)(aptr[1] + kt);
            rb0 = *(const float4*)(bp + (size_t)kt * idim);
            rb1 = *(const float4*)(bp + (size_t)(kt + 8) * idim);
        }
        {
            uint32_t ao = p * A_SZB, bo = p * B_SZB;
            unsigned ah[2][4];
            ldsm4(ah[0], a_ld[0] + ao); ldsm4(ah[1], a_ld[1] + ao);
            #pragma unroll
            for (int np = 0; np < 2; np++) {
                unsigned bg[4], bu[4];
                ldsm4t(bg, b_ld[0][np] + bo);
                ldsm4t(bu, b_ld[1][np] + bo);
                #pragma unroll
                for (int j = 0; j < 2; j++) {
                    int nt = np * 2 + j;
                    #pragma unroll
                    for (int mt = 0; mt < 2; mt++) {
                        mma_f16(accg[mt][nt], ah[mt], &bg[2 * j]);
                        mma_f16(accu[mt][nt], ah[mt], &bu[2 * j]);
                    }
                }
            }
        }
        if (more) {
            int q = p ^ 1;
            unsigned short* Bq = mat ? Bu[q] : Bg[q];
            *(uint2*)&Ah[q][mA[0] * A_STR + kA[0]] =
                make_uint2(pack2h(ra0.x, ra0.y), pack2h(ra0.z, ra0.w));
            *(uint2*)&Ah[q][mA[1] * A_STR + kA[1]] =
                make_uint2(pack2h(ra1.x, ra1.y), pack2h(ra1.z, ra1.w));
            *(uint2*)&Bq[kr * B_STR + nq] =
                make_uint2(pack2h(rb0.x, rb0.y), pack2h(rb0.z, rb0.w));
            *(uint2*)&Bq[(kr + 8) * B_STR + nq] =
                make_uint2(pack2h(rb1.x, rb1.y), pack2h(rb1.z, rb1.w));
        }
        __syncthreads();
    }

    // epilogue: silu(gate) * up -> fp32 H
    #pragma unroll
    for (int mt = 0; mt < 2; mt++) {
        #pragma unroll
        for (int half = 0; half < 2; half++) {
            int r = m0 + warpM * 32 + mt * 16 + half * 8 + gq;
            if (r >= cnt) continue;
            float* hrow = H + (size_t)(off + r) * idim + n0 + warpN * 32;
            #pragma unroll
            for (int nt = 0; nt < 4; nt++) {
                float gv0 = accg[mt][nt][half * 2 + 0];
                float gv1 = accg[mt][nt][half * 2 + 1];
                float uv0 = accu[mt][nt][half * 2 + 0];
                float uv1 = accu[mt][nt][half * 2 + 1];
                float2 hv;
                hv.x = gv0 / (1.f + expf(-gv0)) * uv0;
                hv.y = gv1 / (1.f + expf(-gv1)) * uv1;
                *(float2*)&hrow[nt * 8 + 2 * tq] = hv;
            }
        }
    }
}

// ---------------- GEMM 2: out += w * H @ Wd  (out pre-zeroed; all atomic) ----
__global__ void __launch_bounds__(256, 2)
gemm_down_all(const float* __restrict__ Wd, const float* __restrict__ SWd,
              float* __restrict__ out) {
    int z = blockIdx.z;
    bool shared_e = (z < 2);
    int cnt, off, astride, kbase;
    const float* wd;
    const float* Hsrc;
    if (shared_e) {
        cnt = NT; off = 0; astride = NSI; kbase = z * NI;  // K-half of NSI
        wd = SWd + (size_t)kbase * ND;
        Hsrc = g_hs;
    } else {
        int e = z - 2;
        cnt = g_counts[e]; off = g_offsets[e]; astride = NI; kbase = 0;
        wd = Wd + (size_t)e * NI * ND;
        Hsrc = g_h;
    }
    int m0 = blockIdx.x * 128;
    if (m0 >= cnt) return;
    int n0 = blockIdx.y * 64;

    __shared__ __align__(16) unsigned short Ah[2][A_SZ];
    __shared__ __align__(16) unsigned short Bh[2][B_SZ];

    int tid  = threadIdx.x;
    int lane = tid & 31, wid = tid >> 5;
    int warpM = wid >> 1, warpN = wid & 1;
    int gq = lane >> 2, tq = lane & 3;

    const float* aptr[2]; int mA[2], kA[2];
    #pragma unroll
    for (int l = 0; l < 2; l++) {
        int idx = tid + l * 256;
        mA[l] = idx >> 2; kA[l] = (idx & 3) << 2;
        int m = m0 + mA[l];
        int hr = (m < cnt) ? (off + m) : off;
        aptr[l] = Hsrc + (size_t)hr * astride + kbase + kA[l];
    }
    int kr = tid >> 4, nq = (tid & 15) << 2;
    const float* bp = wd + (size_t)kr * ND + n0 + nq;

    int arow = lane & 15, acolb = (lane >> 4) << 4;
    uint32_t a_ld[2];
    #pragma unroll
    for (int mt = 0; mt < 2; mt++) {
        int r = warpM * 32 + mt * 16 + arow;
        a_ld[mt] = sptr(Ah) + r * (A_STR * 2) + acolb;
    }
    int bkr = lane & 15;
    int bcolb = (warpN * 32) * 2 + ((lane >> 4) << 4);
    uint32_t b_ld[2];
    #pragma unroll
    for (int np = 0; np < 2; np++)
        b_ld[np] = sptr(Bh) + bkr * (B_STR * 2) + bcolb + np * 32;

    float acc[2][4][4];
    #pragma unroll
    for (int mt = 0; mt < 2; mt++)
        #pragma unroll
        for (int nt = 0; nt < 4; nt++)
            #pragma unroll
            for (int r = 0; r < 4; r++) acc[mt][nt][r] = 0.f;

    float4 ra0 = *(const float4*)(aptr[0]);
    float4 ra1 = *(const float4*)(aptr[1]);
    float4 rb  = *(const float4*)(bp);
    {
        *(uint2*)&Ah[0][mA[0] * A_STR + kA[0]] =
            make_uint2(pack2h(ra0.x, ra0.y), pack2h(ra0.z, ra0.w));
        *(uint2*)&Ah[0][mA[1] * A_STR + kA[1]] =
            make_uint2(pack2h(ra1.x, ra1.y), pack2h(ra1.z, ra1.w));
        *(uint2*)&Bh[0][kr * B_STR + nq] =
            make_uint2(pack2h(rb.x, rb.y), pack2h(rb.z, rb.w));
    }
    __syncthreads();

    const int NCH = NI / 16;   // 88 chunks for ALL blocks (uniform duration)
    for (int c = 0; c < NCH; c++) {
        int p = c & 1;
        bool more = (c + 1 < NCH);
        if (more) {
            int kt = (c + 1) * 16;
            ra0 = *(const float4*)(aptr[0] + kt);
            ra1 = *(const float4*)(aptr[1] + kt);
            rb  = *(const float4*)(bp + (size_t)kt * ND);
        }
        {
            uint32_t ao = p * A_SZB, bo = p * B_SZB;
            unsigned ah[2][4];
            ldsm4(ah[0], a_ld[0] + ao); ldsm4(ah[1], a_ld[1] + ao);
            #pragma unroll
            for (int np = 0; np < 2; np++) {
                unsigned bh[4];
                ldsm4t(bh, b_ld[np] + bo);
                #pragma unroll
                for (int j = 0; j < 2; j++) {
                    int nt = np * 2 + j;
                    #pragma unroll
                    for (int mt = 0; mt < 2; mt++)
                        mma_f16(acc[mt][nt], ah[mt], &bh[2 * j]);
                }
            }
        }
        if (more) {
            int q = p ^ 1;
            *(uint2*)&Ah[q][mA[0] * A_STR + kA[0]] =
                make_uint2(pack2h(ra0.x, ra0.y), pack2h(ra0.z, ra0.w));
            *(uint2*)&Ah[q][mA[1] * A_STR + kA[1]] =
                make_uint2(pack2h(ra1.x, ra1.y), pack2h(ra1.z, ra1.w));
            *(uint2*)&Bh[q][kr * B_STR + nq] =
                make_uint2(pack2h(rb.x, rb.y), pack2h(rb.z, rb.w));
        }
        __syncthreads();
    }

    // epilogue: atomic accumulate (out pre-zeroed by memset)
    #pragma unroll
    for (int mt = 0; mt < 2; mt++) {
        #pragma unroll
        for (int half = 0; half < 2; half++) {
            int r = m0 + warpM * 32 + mt * 16 + half * 8 + gq;
            if (r >= cnt) continue;
            int tok; float w;
            if (shared_e) { tok = r; w = 1.0f; }
            else {
                int grow = off + r;
                tok = g_rowlist[grow];
                w   = g_roww[grow] * 2.5f;
            }
            float* op = out + (size_t)tok * ND + n0 + warpN * 32;
            #pragma unroll
            for (int nt = 0; nt < 4; nt++) {
                atomicAdd(&op[nt * 8 + 2 * tq],     w * acc[mt][nt][half * 2 + 0]);
                atomicAdd(&op[nt * 8 + 2 * tq + 1], w * acc[mt][nt][half * 2 + 1]);
            }
        }
    }
}

// ---------------- launch ----------------
extern "C" void kernel_launch(void* const* d_in, const int* in_sizes, int n_in,
                              void* d_out, int out_size) {
    const float* x       = (const float*)d_in[0];
    const float* gate_w  = (const float*)d_in[1];
    const float* gate_b  = (const float*)d_in[2];
    const float* w_gate  = (const float*)d_in[3];
    const float* w_up    = (const float*)d_in[4];
    const float* w_down  = (const float*)d_in[5];
    const float* sw_gate = (const float*)d_in[6];
    const float* sw_up   = (const float*)d_in[7];
    const float* sw_down = (const float*)d_in[8];
    float* out = (float*)d_out;

    gate_kernel <<<NT, 256>>>(x, gate_w, gate_b);
    route_kernel<<<1, 1024>>>();

    // gated: z=0,1 shared n-slices; z=2..33 routed experts. No dead n-blocks.
    gemm_gated_all<<<dim3(NT / 128, 22, NE + 2), 256>>>(
        x, w_gate, w_up, sw_gate, sw_up);

    // down: out zero-init, then all paths atomically accumulate.
    cudaMemsetAsync(out, 0, (size_t)out_size * sizeof(float));
    gemm_down_all<<<dim3(NT / 128, ND / 64, NE + 2), 256>>>(
        w_down, sw_down, out);
}

// round 17
// speedup vs baseline: 1.7802x; 1.4427x over previous
#include <cuda_runtime.h>
#include <cuda_fp16.h>
#include <math.h>
#include <stdint.h>

// Problem constants
#define NT   1024          // tokens
#define ND   2048          // hidden dim
#define NE   32            // experts
#define NI   1408          // routed intermediate
#define NSI  2816          // shared intermediate
#define NG   8             // groups
#define EPG  4             // experts per group
#define NA   (NT * 4)      // total assignments (top_k = 4)

// ---------------- device scratch ----------------
__device__ float g_h [NA * NI];    // routed  silu(x@Wg)*(x@Wu)  (fp32)
__device__ float g_hs[NT * NSI];   // shared  silu(x@Sg)*(x@Su)
__device__ int   g_rowlist[NA];
__device__ float g_roww  [NA];
__device__ int   g_counts [NE];
__device__ int   g_offsets[NE];
__device__ int   g_tid4[NA];
__device__ float g_tw4 [NA];

// ---------------- fp16 helpers ----------------
__device__ __forceinline__ unsigned pack2h(float v0, float v1) {
    __half2 hh = __floats2half2_rn(v0, v1);
    return *(unsigned*)&hh;
}

__device__ __forceinline__ void mma_f16(float* d, const unsigned* a, const unsigned* b) {
    asm volatile(
        "mma.sync.aligned.m16n8k16.row.col.f32.f16.f16.f32 "
        "{%0,%1,%2,%3}, {%4,%5,%6,%7}, {%8,%9}, {%0,%1,%2,%3};"
        : "+f"(d[0]), "+f"(d[1]), "+f"(d[2]), "+f"(d[3])
        : "r"(a[0]), "r"(a[1]), "r"(a[2]), "r"(a[3]), "r"(b[0]), "r"(b[1]));
}

__device__ __forceinline__ void ldsm4(unsigned* r, uint32_t a) {
    asm volatile("ldmatrix.sync.aligned.m8n8.x4.shared.b16 {%0,%1,%2,%3}, [%4];"
        : "=r"(r[0]), "=r"(r[1]), "=r"(r[2]), "=r"(r[3]) : "r"(a));
}
__device__ __forceinline__ void ldsm4t(unsigned* r, uint32_t a) {
    asm volatile("ldmatrix.sync.aligned.m8n8.x4.trans.shared.b16 {%0,%1,%2,%3}, [%4];"
        : "=r"(r[0]), "=r"(r[1]), "=r"(r[2]), "=r"(r[3]) : "r"(a));
}
__device__ __forceinline__ uint32_t sptr(const void* p) {
    return (uint32_t)__cvta_generic_to_shared(p);
}

// ---------------- routing kernels ----------------
__global__ void gate_kernel(const float* __restrict__ x,
                            const float* __restrict__ gw,
                            const float* __restrict__ gb) {
    __shared__ float xs[ND];
    __shared__ float logit[NE];
    int t = blockIdx.x;
    for (int k = threadIdx.x; k < ND; k += 256) xs[k] = x[(size_t)t * ND + k];
    __syncthreads();
    int e = threadIdx.x >> 3;
    int j = threadIdx.x & 7;
    const float* w = gw + (size_t)e * ND;
    float s = 0.f;
    for (int k = j; k < ND; k += 8) s += xs[k] * w[k];
    s += __shfl_xor_sync(0xffffffffu, s, 1);
    s += __shfl_xor_sync(0xffffffffu, s, 2);
    s += __shfl_xor_sync(0xffffffffu, s, 4);
    if (j == 0) logit[e] = s + gb[e];
    __syncthreads();
    if (threadIdx.x == 0) {
        float sc[NE], scb[NE];
        #pragma unroll
        for (int i = 0; i < NE; i++) {
            float v = 1.f / (1.f + expf(-logit[i]));
            sc[i]  = v;
            scb[i] = v + gb[i];
        }
        float gs[NG];
        #pragma unroll
        for (int g = 0; g < NG; g++) {
            float m1 = -1e30f, m2 = -1e30f;
            #pragma unroll
            for (int q = 0; q < EPG; q++) {
                float v = scb[g * EPG + q];
                if (v > m1) { m2 = m1; m1 = v; } else if (v > m2) { m2 = v; }
            }
            gs[g] = m1 + m2;
        }
        bool gsel[NG];
        #pragma unroll
        for (int g = 0; g < NG; g++) gsel[g] = false;
        for (int r = 0; r < 4; r++) {
            float best = -1e30f; int bi = 0;
            for (int g = 0; g < NG; g++)
                if (!gsel[g] && gs[g] > best) { best = gs[g]; bi = g; }
            gsel[bi] = true;
        }
        float tmp[NE];
        #pragma unroll
        for (int i = 0; i < NE; i++) tmp[i] = gsel[i / EPG] ? scb[i] : 0.0f;
        int ids[4]; float tw[4]; float wsum = 0.f;
        for (int r = 0; r < 4; r++) {
            float best = -1e30f; int bi = 0;
            for (int i = 0; i < NE; i++)
                if (tmp[i] > best) { best = tmp[i]; bi = i; }
            tmp[bi] = -1e30f;
            ids[r] = bi;
            tw[r] = sc[bi];
            wsum += tw[r];
        }
        float inv = 1.f / wsum;
        for (int r = 0; r < 4; r++) {
            g_tid4[t * 4 + r] = ids[r];
            g_tw4 [t * 4 + r] = tw[r] * inv;
        }
    }
}

// fused count + scan + scatter, single block of 1024 threads
__global__ void route_kernel() {
    __shared__ int cnts[NE];
    __shared__ int curs[NE];
    int tid = threadIdx.x;
    if (tid < NE) cnts[tid] = 0;
    __syncthreads();
    for (int i = tid; i < NA; i += 1024)
        atomicAdd(&cnts[g_tid4[i]], 1);
    __syncthreads();
    if (tid < 32) {
        int c = cnts[tid];
        int v = c;
        #pragma unroll
        for (int o = 1; o < 32; o <<= 1) {
            int u = __shfl_up_sync(0xffffffffu, v, o);
            if (tid >= o) v += u;
        }
        g_counts[tid]  = c;
        g_offsets[tid] = v - c;
        curs[tid]      = v - c;
    }
    __syncthreads();
    for (int i = tid; i < NA; i += 1024) {
        int e = g_tid4[i];
        int pos = atomicAdd(&curs[e], 1);
        g_rowlist[pos] = i >> 2;
        g_roww[pos]    = g_tw4[i];
    }
}

// ============================================================================
// Pure fp16 mma.sync GEMMs, LDSM fragments, 2-stage SMEM ping-pong with
// REGISTER PREFETCH DISTANCE 2 (two prefetch register sets, loop unrolled x2):
//   iter c: LDG(c+2)->R[c&1]; mma(stage c&1); STS R[(c+1)&1]->stage (c+1)&1; sync
// LDG issued at iter c is consumed at end of iter c+1 (~2 chunk-times of cover).
// Gated grid (8, 22, 34): z=0,1 shared n-slices (NSI); z>=2 routed (NI).
// Down grid (8, 32, 34): z=0,1 shared K-halves; z>=2 routed. Uniform 88 chunks.
// Block BM=128, BN=64, BK=16; 256 thr = 8 warps (4M x 2N); warp tile 32x32.
// ============================================================================

#define A_STR 24
#define B_STR 72
#define A_SZ  (128 * A_STR)
#define B_SZ  (16 * B_STR)
#define A_SZB (A_SZ * 2)
#define B_SZB (B_SZ * 2)

// ---------------- GEMM 1: H = silu(A@Wg) * (A@Wu) ----------------
__global__ void __launch_bounds__(256, 2)
gemm_gated_all(const float* __restrict__ x,
               const float* __restrict__ Wg,  const float* __restrict__ Wu,
               const float* __restrict__ SWg, const float* __restrict__ SWu) {
    int z = blockIdx.z;
    bool shared_e = (z < 2);
    int cnt, off, idim, n0;
    const float* wg;
    const float* wu;
    float* H;
    if (shared_e) {
        cnt = NT; off = 0; idim = NSI;
        wg = SWg; wu = SWu; H = g_hs;
        n0 = (z * 22 + blockIdx.y) * 64;
    } else {
        int e = z - 2;
        cnt = g_counts[e]; off = g_offsets[e]; idim = NI;
        wg = Wg + (size_t)e * ND * NI;
        wu = Wu + (size_t)e * ND * NI;
        H = g_h;
        n0 = blockIdx.y * 64;
    }
    int m0 = blockIdx.x * 128;
    if (m0 >= cnt) return;

    __shared__ __align__(16) unsigned short Ah[2][A_SZ];
    __shared__ __align__(16) unsigned short Bg[2][B_SZ], Bu[2][B_SZ];

    int tid  = threadIdx.x;
    int lane = tid & 31, wid = tid >> 5;
    int warpM = wid >> 1, warpN = wid & 1;
    int gq = lane >> 2, tq = lane & 3;

    // ---- A staging: 2 float4 per thread over 128x16 fp32 ----
    const float* aptr[2]; int mA[2], kA[2];
    #pragma unroll
    for (int l = 0; l < 2; l++) {
        int idx = tid + l * 256;
        mA[l] = idx >> 2; kA[l] = (idx & 3) << 2;
        int m = m0 + mA[l];
        int tok;
        if (shared_e) tok = (m < cnt) ? m : 0;
        else          tok = (m < cnt) ? g_rowlist[off + m] : 0;
        aptr[l] = x + (size_t)tok * ND + kA[l];
    }
    // ---- B staging: 2 matrices x 128 threads; rows kr, kr+8; 4 n-vals ----
    int mat = tid >> 7, rr = tid & 127;
    int kr  = rr >> 4, nq = (rr & 15) << 2;
    const float* bp = (mat ? wu : wg) + (size_t)kr * idim + n0 + nq;

    // ---- LDSM base addresses ----
    int arow = lane & 15, acolb = (lane >> 4) << 4;
    uint32_t a_ld[2];
    #pragma unroll
    for (int mt = 0; mt < 2; mt++) {
        int r = warpM * 32 + mt * 16 + arow;
        a_ld[mt] = sptr(Ah) + r * (A_STR * 2) + acolb;
    }
    int bkr = lane & 15;
    int bcolb = (warpN * 32) * 2 + ((lane >> 4) << 4);
    uint32_t b_ld[2][2];
    const void* barr[2] = {Bg, Bu};
    #pragma unroll
    for (int a = 0; a < 2; a++)
        #pragma unroll
        for (int np = 0; np < 2; np++)
            b_ld[a][np] = sptr(barr[a]) + bkr * (B_STR * 2) + bcolb + np * 32;

    float accg[2][4][4], accu[2][4][4];
    #pragma unroll
    for (int mt = 0; mt < 2; mt++)
        #pragma unroll
        for (int nt = 0; nt < 4; nt++)
            #pragma unroll
            for (int r = 0; r < 4; r++) { accg[mt][nt][r] = 0.f; accu[mt][nt][r] = 0.f; }

    // two prefetch register sets
    float4 raA0, raA1, rbA0, rbA1;   // set A
    float4 raB0, raB1, rbB0, rbB1;   // set B

    auto loadA = [&](int c) {
        int kt = c * 16;
        raA0 = *(const float4*)(aptr[0] + kt);
        raA1 = *(const float4*)(aptr[1] + kt);
        rbA0 = *(const float4*)(bp + (size_t)kt * idim);
        rbA1 = *(const float4*)(bp + (size_t)(kt + 8) * idim);
    };
    auto loadB = [&](int c) {
        int kt = c * 16;
        raB0 = *(const float4*)(aptr[0] + kt);
        raB1 = *(const float4*)(aptr[1] + kt);
        rbB0 = *(const float4*)(bp + (size_t)kt * idim);
        rbB1 = *(const float4*)(bp + (size_t)(kt + 8) * idim);
    };
    unsigned short* Bsel[2] = { mat ? Bu[0] : Bg[0], mat ? Bu[1] : Bg[1] };
    auto storeA = [&](int s) {
        *(uint2*)&Ah[s][mA[0] * A_STR + kA[0]] =
            make_uint2(pack2h(raA0.x, raA0.y), pack2h(raA0.z, raA0.w));
        *(uint2*)&Ah[s][mA[1] * A_STR + kA[1]] =
            make_uint2(pack2h(raA1.x, raA1.y), pack2h(raA1.z, raA1.w));
        *(uint2*)&Bsel[s][kr * B_STR + nq] =
            make_uint2(pack2h(rbA0.x, rbA0.y), pack2h(rbA0.z, rbA0.w));
        *(uint2*)&Bsel[s][(kr + 8) * B_STR + nq] =
            make_uint2(pack2h(rbA1.x, rbA1.y), pack2h(rbA1.z, rbA1.w));
    };
    auto storeB = [&](int s) {
        *(uint2*)&Ah[s][mA[0] * A_STR + kA[0]] =
            make_uint2(pack2h(raB0.x, raB0.y), pack2h(raB0.z, raB0.w));
        *(uint2*)&Ah[s][mA[1] * A_STR + kA[1]] =
            make_uint2(pack2h(raB1.x, raB1.y), pack2h(raB1.z, raB1.w));
        *(uint2*)&Bsel[s][kr * B_STR + nq] =
            make_uint2(pack2h(rbB0.x, rbB0.y), pack2h(rbB0.z, rbB0.w));
        *(uint2*)&Bsel[s][(kr + 8) * B_STR + nq] =
            make_uint2(pack2h(rbB1.x, rbB1.y), pack2h(rbB1.z, rbB1.w));
    };
    auto do_mma = [&](int s) {
        uint32_t ao = s * A_SZB, bo = s * B_SZB;
        unsigned ah[2][4];
        ldsm4(ah[0], a_ld[0] + ao); ldsm4(ah[1], a_ld[1] + ao);
        #pragma unroll
        for (int np = 0; np < 2; np++) {
            unsigned bg[4], bu[4];
            ldsm4t(bg, b_ld[0][np] + bo);
            ldsm4t(bu, b_ld[1][np] + bo);
            #pragma unroll
            for (int j = 0; j < 2; j++) {
                int nt = np * 2 + j;
                #pragma unroll
                for (int mt = 0; mt < 2; mt++) {
                    mma_f16(accg[mt][nt], ah[mt], &bg[2 * j]);
                    mma_f16(accu[mt][nt], ah[mt], &bu[2 * j]);
                }
            }
        }
    };

    // prologue: chunk0 -> stage0 (set A); chunk1 -> set B
    loadA(0); storeA(0);
    loadB(1);
    __syncthreads();

    const int NCH = ND / 16;   // 128, even
    for (int c = 0; c < NCH; c += 2) {
        // even iter: mma stage0; prefetch c+2 -> setA; store setB(chunk c+1) -> stage1
        if (c + 2 < NCH) loadA(c + 2);
        do_mma(0);
        storeB(1);
        __syncthreads();
        // odd iter: mma stage1; prefetch c+3 -> setB; store setA(chunk c+2) -> stage0
        if (c + 3 < NCH) loadB(c + 3);
        do_mma(1);
        if (c + 2 < NCH) storeA(0);
        __syncthreads();
    }

    // epilogue: silu(gate) * up -> fp32 H
    #pragma unroll
    for (int mt = 0; mt < 2; mt++) {
        #pragma unroll
        for (int half = 0; half < 2; half++) {
            int r = m0 + warpM * 32 + mt * 16 + half * 8 + gq;
            if (r >= cnt) continue;
            float* hrow = H + (size_t)(off + r) * idim + n0 + warpN * 32;
            #pragma unroll
            for (int nt = 0; nt < 4; nt++) {
                float gv0 = accg[mt][nt][half * 2 + 0];
                float gv1 = accg[mt][nt][half * 2 + 1];
                float uv0 = accu[mt][nt][half * 2 + 0];
                float uv1 = accu[mt][nt][half * 2 + 1];
                float2 hv;
                hv.x = gv0 / (1.f + expf(-gv0)) * uv0;
                hv.y = gv1 / (1.f + expf(-gv1)) * uv1;
                *(float2*)&hrow[nt * 8 + 2 * tq] = hv;
            }
        }
    }
}

// ---------------- GEMM 2: out += w * H @ Wd  (out pre-zeroed; all atomic) ----
__global__ void __launch_bounds__(256, 2)
gemm_down_all(const float* __restrict__ Wd, const float* __restrict__ SWd,
              float* __restrict__ out) {
    int z = blockIdx.z;
    bool shared_e = (z < 2);
    int cnt, off, astride, kbase;
    const float* wd;
    const float* Hsrc;
    if (shared_e) {
        cnt = NT; off = 0; astride = NSI; kbase = z * NI;  // K-half of NSI
        wd = SWd + (size_t)kbase * ND;
        Hsrc = g_hs;
    } else {
        int e = z - 2;
        cnt = g_counts[e]; off = g_offsets[e]; astride = NI; kbase = 0;
        wd = Wd + (size_t)e * NI * ND;
        Hsrc = g_h;
    }
    int m0 = blockIdx.x * 128;
    if (m0 >= cnt) return;
    int n0 = blockIdx.y * 64;

    __shared__ __align__(16) unsigned short Ah[2][A_SZ];
    __shared__ __align__(16) unsigned short Bh[2][B_SZ];

    int tid  = threadIdx.x;
    int lane = tid & 31, wid = tid >> 5;
    int warpM = wid >> 1, warpN = wid & 1;
    int gq = lane >> 2, tq = lane & 3;

    const float* aptr[2]; int mA[2], kA[2];
    #pragma unroll
    for (int l = 0; l < 2; l++) {
        int idx = tid + l * 256;
        mA[l] = idx >> 2; kA[l] = (idx & 3) << 2;
        int m = m0 + mA[l];
        int hr = (m < cnt) ? (off + m) : off;
        aptr[l] = Hsrc + (size_t)hr * astride + kbase + kA[l];
    }
    int kr = tid >> 4, nq = (tid & 15) << 2;
    const float* bp = wd + (size_t)kr * ND + n0 + nq;

    int arow = lane & 15, acolb = (lane >> 4) << 4;
    uint32_t a_ld[2];
    #pragma unroll
    for (int mt = 0; mt < 2; mt++) {
        int r = warpM * 32 + mt * 16 + arow;
        a_ld[mt] = sptr(Ah) + r * (A_STR * 2) + acolb;
    }
    int bkr = lane & 15;
    int bcolb = (warpN * 32) * 2 + ((lane >> 4) << 4);
    uint32_t b_ld[2];
    #pragma unroll
    for (int np = 0; np < 2; np++)
        b_ld[np] = sptr(Bh) + bkr * (B_STR * 2) + bcolb + np * 32;

    float acc[2][4][4];
    #pragma unroll
    for (int mt = 0; mt < 2; mt++)
        #pragma unroll
        for (int nt = 0; nt < 4; nt++)
            #pragma unroll
            for (int r = 0; r < 4; r++) acc[mt][nt][r] = 0.f;

    // two prefetch register sets
    float4 raA0, raA1, rbA;
    float4 raB0, raB1, rbB;

    auto loadA = [&](int c) {
        int kt = c * 16;
        raA0 = *(const float4*)(aptr[0] + kt);
        raA1 = *(const float4*)(aptr[1] + kt);
        rbA  = *(const float4*)(bp + (size_t)kt * ND);
    };
    auto loadB = [&](int c) {
        int kt = c * 16;
        raB0 = *(const float4*)(aptr[0] + kt);
        raB1 = *(const float4*)(aptr[1] + kt);
        rbB  = *(const float4*)(bp + (size_t)kt * ND);
    };
    auto storeA = [&](int s) {
        *(uint2*)&Ah[s][mA[0] * A_STR + kA[0]] =
            make_uint2(pack2h(raA0.x, raA0.y), pack2h(raA0.z, raA0.w));
        *(uint2*)&Ah[s][mA[1] * A_STR + kA[1]] =
            make_uint2(pack2h(raA1.x, raA1.y), pack2h(raA1.z, raA1.w));
        *(uint2*)&Bh[s][kr * B_STR + nq] =
            make_uint2(pack2h(rbA.x, rbA.y), pack2h(rbA.z, rbA.w));
    };
    auto storeB = [&](int s) {
        *(uint2*)&Ah[s][mA[0] * A_STR + kA[0]] =
            make_uint2(pack2h(raB0.x, raB0.y), pack2h(raB0.z, raB0.w));
        *(uint2*)&Ah[s][mA[1] * A_STR + kA[1]] =
            make_uint2(pack2h(raB1.x, raB1.y), pack2h(raB1.z, raB1.w));
        *(uint2*)&Bh[s][kr * B_STR + nq] =
            make_uint2(pack2h(rbB.x, rbB.y), pack2h(rbB.z, rbB.w));
    };
    auto do_mma = [&](int s) {
        uint32_t ao = s * A_SZB, bo = s * B_SZB;
        unsigned ah[2][4];
        ldsm4(ah[0], a_ld[0] + ao); ldsm4(ah[1], a_ld[1] + ao);
        #pragma unroll
        for (int np = 0; np < 2; np++) {
            unsigned bh[4];
            ldsm4t(bh, b_ld[np] + bo);
            #pragma unroll
            for (int j = 0; j < 2; j++) {
                int nt = np * 2 + j;
                #pragma unroll
                for (int mt = 0; mt < 2; mt++)
                    mma_f16(acc[mt][nt], ah[mt], &bh[2 * j]);
            }
        }
    };

    loadA(0); storeA(0);
    loadB(1);
    __syncthreads();

    const int NCH = NI / 16;   // 88, even; uniform for ALL blocks
    for (int c = 0; c < NCH; c += 2) {
        if (c + 2 < NCH) loadA(c + 2);
        do_mma(0);
        storeB(1);
        __syncthreads();
        if (c + 3 < NCH) loadB(c + 3);
        do_mma(1);
        if (c + 2 < NCH) storeA(0);
        __syncthreads();
    }

    // epilogue: atomic accumulate (out pre-zeroed by memset)
    #pragma unroll
    for (int mt = 0; mt < 2; mt++) {
        #pragma unroll
        for (int half = 0; half < 2; half++) {
            int r = m0 + warpM * 32 + mt * 16 + half * 8 + gq;
            if (r >= cnt) continue;
            int tok; float w;
            if (shared_e) { tok = r; w = 1.0f; }
            else {
                int grow = off + r;
                tok = g_rowlist[grow];
                w   = g_roww[grow] * 2.5f;
            }
            float* op = out + (size_t)tok * ND + n0 + warpN * 32;
            #pragma unroll
            for (int nt = 0; nt < 4; nt++) {
                atomicAdd(&op[nt * 8 + 2 * tq],     w * acc[mt][nt][half * 2 + 0]);
                atomicAdd(&op[nt * 8 + 2 * tq + 1], w * acc[mt][nt][half * 2 + 1]);
            }
        }
    }
}

// ---------------- launch ----------------
extern "C" void kernel_launch(void* const* d_in, const int* in_sizes, int n_in,
                              void* d_out, int out_size) {
    const float* x       = (const float*)d_in[0];
    const float* gate_w  = (const float*)d_in[1];
    const float* gate_b  = (const float*)d_in[2];
    const float* w_gate  = (const float*)d_in[3];
    const float* w_up    = (const float*)d_in[4];
    const float* w_down  = (const float*)d_in[5];
    const float* sw_gate = (const float*)d_in[6];
    const float* sw_up   = (const float*)d_in[7];
    const float* sw_down = (const float*)d_in[8];
    float* out = (float*)d_out;

    gate_kernel <<<NT, 256>>>(x, gate_w, gate_b);
    route_kernel<<<1, 1024>>>();

    // gated: z=0,1 shared n-slices; z=2..33 routed experts. No dead n-blocks.
    gemm_gated_all<<<dim3(NT / 128, 22, NE + 2), 256>>>(
        x, w_gate, w_up, sw_gate, sw_up);

    // down: out zero-init, then all paths atomically accumulate.
    cudaMemsetAsync(out, 0, (size_t)out_size * sizeof(float));
    gemm_down_all<<<dim3(NT / 128, ND / 64, NE + 2), 256>>>(
        w_down, sw_down, out);
}